// round 4
// baseline (speedup 1.0000x reference)
#include <cuda_runtime.h>
#include <cstdint>
#include <math.h>

#define HN 64
#define HE 64
#define NNODE 50000
#define NEDGE 200000
#define NTRI  600000
#define CC 128          // 2*HE
#define D3 320          // 3*HN + 2*HE
#define EPSF 1e-5f

// ---------------- scratch (static device arrays; no allocation) ----------------
__device__ float g_y2[(size_t)NEDGE * CC];    // c2 pre-BN linear out (E,128)
__device__ float g_y3[(size_t)NTRI * CC];     // c3 pre-BN linear out (T,128)
__device__ float g_g2[(size_t)NEDGE * HE];    // sigmoid*tanh of c2 (E,64)
__device__ float g_agg[(size_t)NEDGE * HE];   // segment-summed msg (E,64)
// sums: [0:128) c2 sum, [128:256) c2 sq, [256:384) c3 sum, [384:512) c3 sq,
//       [512:576) g2 sum, [576:640) g2 sq, [640:704) agg sum, [704:768) agg sq
__device__ float g_sumbuf[768];
// ab: (a,b) affine coefficients per BN: y*a + b  (same layout)
__device__ float g_ab[768];

// ---------------- packed f32x2 helpers (sm_103a FFMA2 path) ----------------
__device__ __forceinline__ unsigned long long fma2(unsigned long long a,
                                                   unsigned long long b,
                                                   unsigned long long c) {
    unsigned long long d;
    asm("fma.rn.f32x2 %0, %1, %2, %3;" : "=l"(d) : "l"(a), "l"(b), "l"(c));
    return d;
}
__device__ __forceinline__ unsigned long long pack2(float lo, float hi) {
    unsigned long long d;
    asm("mov.b64 %0, {%1, %2};" : "=l"(d) : "f"(lo), "f"(hi));
    return d;
}
__device__ __forceinline__ float2 unpack2(unsigned long long v) {
    float2 r;
    asm("mov.b64 {%0, %1}, %2;" : "=f"(r.x), "=f"(r.y) : "l"(v));
    return r;
}

__device__ __forceinline__ float sigmoidf_(float x) {
    return 1.0f / (1.0f + __expf(-x));
}

// W shared-layout permutation: thread cg (0..15) owns cols cg*8..cg*8+7.
// Col c stored at ((c>>3)<<2) + (q&3) + ((q&4)<<4), q=c&7: each 16B load
// across 16 lanes is a contiguous 256B conflict-free block.
__device__ __forceinline__ int wpos(int c) {
    int q = c & 7;
    return ((c >> 3) << 2) + (q & 3) + ((q & 4) << 4);
}

// ============================================================================
// K0: zero g_agg and stat sums
// ============================================================================
__global__ void k_zero() {
    size_t i = (size_t)blockIdx.x * blockDim.x + threadIdx.x;
    size_t stride = (size_t)gridDim.x * blockDim.x;
    size_t n = (size_t)NEDGE * HE / 4;
    float4 z = make_float4(0.f, 0.f, 0.f, 0.f);
    float4* p4 = (float4*)g_agg;
    for (size_t p = i; p < n; p += stride) p4[p] = z;
    if (i < 768) g_sumbuf[i] = 0.0f;
}

// ============================================================================
// K1: c2 linear.  x = node[i]*node[j] (64), y = W2 x + b2 (128).
// 64-edge tiles, 256 threads, 4 rows/thread. FFMA2 inner loop.
// ============================================================================
__global__ void __launch_bounds__(256) k_c2mm(const float* __restrict__ node,
                                              const int* __restrict__ vi,
                                              const int* __restrict__ vj,
                                              const float* __restrict__ W2,
                                              const float* __restrict__ b2) {
    extern __shared__ __align__(16) float smem2[];
    float* sw = smem2;               // 64*128 floats (32KB)
    float* sx = smem2 + 64 * CC;     // 64*72 floats (18KB)
    __shared__ float sred[256];
    const int tid = threadIdx.x;

    for (int idx = tid; idx < 64 * 128; idx += 256) {
        int c = idx >> 6, k = idx & 63;
        sw[(k << 7) + wpos(c)] = W2[idx];
    }
    sred[tid] = 0.0f;

    const int cg = tid & 15;
    const int rg = tid >> 4;       // 0..15
    const int l8 = tid & 7;
    float bb[8];
#pragma unroll
    for (int m = 0; m < 8; m++) bb[m] = b2[cg * 8 + m];

    float sum[8], sq[8];
#pragma unroll
    for (int m = 0; m < 8; m++) { sum[m] = 0.0f; sq[m] = 0.0f; }

    const int ntiles = NEDGE / 64;
    for (int tile = blockIdx.x; tile < ntiles; tile += gridDim.x) {
        const int ebase = tile << 6;
        __syncthreads();
        // gather: 8 threads per edge, 64 edges → 2 passes
        for (int p = tid >> 3; p < 64; p += 32) {
            int e = ebase + p;
            const float4* a = (const float4*)(node + (size_t)vi[e] * HN) + l8 * 2;
            const float4* b = (const float4*)(node + (size_t)vj[e] * HN) + l8 * 2;
            float4 a0 = a[0], a1 = a[1];
            float4 b0 = b[0], b1 = b[1];
            float* dst = sx + p * 72 + l8 * 8;
            *(float4*)dst = make_float4(a0.x * b0.x, a0.y * b0.y, a0.z * b0.z, a0.w * b0.w);
            *(float4*)(dst + 4) = make_float4(a1.x * b1.x, a1.y * b1.y, a1.z * b1.z, a1.w * b1.w);
        }
        __syncthreads();

        unsigned long long acc[4][4];
#pragma unroll
        for (int r = 0; r < 4; r++)
#pragma unroll
            for (int p = 0; p < 4; p++) acc[r][p] = 0ull;
        const float* xp0 = sx + rg * 72;

#pragma unroll 2
        for (int k = 0; k < 64; k += 4) {
            float4 xv[4];
            xv[0] = *(const float4*)(xp0 + k);
            xv[1] = *(const float4*)(xp0 + 16 * 72 + k);
            xv[2] = *(const float4*)(xp0 + 32 * 72 + k);
            xv[3] = *(const float4*)(xp0 + 48 * 72 + k);
#pragma unroll
            for (int u = 0; u < 4; u++) {
                const float* wr = sw + ((k + u) << 7) + cg * 4;
                ulonglong2 wa = *(const ulonglong2*)(wr);
                ulonglong2 wb = *(const ulonglong2*)(wr + 64);
#pragma unroll
                for (int r = 0; r < 4; r++) {
                    float f = (u == 0) ? xv[r].x : (u == 1) ? xv[r].y : (u == 2) ? xv[r].z : xv[r].w;
                    unsigned long long xx = pack2(f, f);
                    acc[r][0] = fma2(xx, wa.x, acc[r][0]);
                    acc[r][1] = fma2(xx, wa.y, acc[r][1]);
                    acc[r][2] = fma2(xx, wb.x, acc[r][2]);
                    acc[r][3] = fma2(xx, wb.y, acc[r][3]);
                }
            }
        }
#pragma unroll
        for (int r = 0; r < 4; r++) {
            float y[8];
#pragma unroll
            for (int p = 0; p < 4; p++) {
                float2 v = unpack2(acc[r][p]);
                y[2 * p] = v.x + bb[2 * p];
                y[2 * p + 1] = v.y + bb[2 * p + 1];
            }
#pragma unroll
            for (int m = 0; m < 8; m++) { sum[m] += y[m]; sq[m] += y[m] * y[m]; }
            size_t row = (size_t)(ebase + rg + r * 16);
            float4* o = (float4*)(g_y2 + row * CC + cg * 8);
            o[0] = make_float4(y[0], y[1], y[2], y[3]);
            o[1] = make_float4(y[4], y[5], y[6], y[7]);
        }
    }
    __syncthreads();
#pragma unroll
    for (int m = 0; m < 8; m++) {
        atomicAdd(&sred[cg * 8 + m], sum[m]);
        atomicAdd(&sred[128 + cg * 8 + m], sq[m]);
    }
    __syncthreads();
    atomicAdd(&g_sumbuf[tid], sred[tid]);   // [0:256) = c2 sum|sq
}

// ============================================================================
// K2: c3 linear. x = concat(node[ii],node[ij],node[ik],edge[iji],edge[ikj]) (320)
// y = W3 x + b3 (128). 48-triplet tiles, 3 rows/thread, W3 resident (160KB).
// ============================================================================
__global__ void __launch_bounds__(256) k_c3mm(const float* __restrict__ node,
                                              const float* __restrict__ edge,
                                              const int* __restrict__ ii,
                                              const int* __restrict__ ij,
                                              const int* __restrict__ ik,
                                              const int* __restrict__ iji,
                                              const int* __restrict__ ikj,
                                              const float* __restrict__ W3,
                                              const float* __restrict__ b3) {
    extern __shared__ __align__(16) float smem[];
    float* sw = smem;                 // 320*128 floats (160KB)
    float* sx = smem + D3 * CC;       // 48*324 floats (62KB)
    __shared__ float sred[256];
    const int tid = threadIdx.x;

    for (int idx = tid; idx < D3 * CC; idx += 256) {
        int c = idx / D3;
        int k = idx - c * D3;
        sw[k * CC + wpos(c)] = W3[idx];
    }
    sred[tid] = 0.0f;

    const int cg = tid & 15;
    const int rg = tid >> 4;         // 0..15
    const int l8 = tid & 7;
    float bb[8];
#pragma unroll
    for (int m = 0; m < 8; m++) bb[m] = b3[cg * 8 + m];

    float sum[8], sq[8];
#pragma unroll
    for (int m = 0; m < 8; m++) { sum[m] = 0.0f; sq[m] = 0.0f; }

    const int ntiles = NTRI / 48;
    for (int tile = blockIdx.x; tile < ntiles; tile += gridDim.x) {
        const int tbase = tile * 48;
        __syncthreads();
        // gather 48 rows x 320 floats: 240 (row,seg) pairs, 8 threads per pair
        for (int p = tid >> 3; p < 240; p += 32) {
            int r = p / 5, s = p - r * 5;
            int t = tbase + r;
            const float* src;
            int gi;
            if (s == 0)      { gi = ii[t];  src = node; }
            else if (s == 1) { gi = ij[t];  src = node; }
            else if (s == 2) { gi = ik[t];  src = node; }
            else if (s == 3) { gi = iji[t]; src = edge; }
            else             { gi = ikj[t]; src = edge; }
            const float4* sp = (const float4*)(src + (size_t)gi * 64) + l8 * 2;
            float4 v0 = sp[0], v1 = sp[1];
            float* dst = sx + r * 324 + s * 64 + l8 * 8;
            *(float4*)dst = v0;
            *(float4*)(dst + 4) = v1;
        }
        __syncthreads();

        unsigned long long acc[3][4];
#pragma unroll
        for (int r = 0; r < 3; r++)
#pragma unroll
            for (int p = 0; p < 4; p++) acc[r][p] = 0ull;
        const float* xp0 = sx + rg * 324;

#pragma unroll 2
        for (int k = 0; k < D3; k += 4) {
            float4 xv[3];
            xv[0] = *(const float4*)(xp0 + k);
            xv[1] = *(const float4*)(xp0 + 16 * 324 + k);
            xv[2] = *(const float4*)(xp0 + 32 * 324 + k);
#pragma unroll
            for (int u = 0; u < 4; u++) {
                const float* wr = sw + (k + u) * CC + cg * 4;
                ulonglong2 wa = *(const ulonglong2*)(wr);
                ulonglong2 wb = *(const ulonglong2*)(wr + 64);
#pragma unroll
                for (int r = 0; r < 3; r++) {
                    float f = (u == 0) ? xv[r].x : (u == 1) ? xv[r].y : (u == 2) ? xv[r].z : xv[r].w;
                    unsigned long long xx = pack2(f, f);
                    acc[r][0] = fma2(xx, wa.x, acc[r][0]);
                    acc[r][1] = fma2(xx, wa.y, acc[r][1]);
                    acc[r][2] = fma2(xx, wb.x, acc[r][2]);
                    acc[r][3] = fma2(xx, wb.y, acc[r][3]);
                }
            }
        }
#pragma unroll
        for (int r = 0; r < 3; r++) {
            float y[8];
#pragma unroll
            for (int p = 0; p < 4; p++) {
                float2 v = unpack2(acc[r][p]);
                y[2 * p] = v.x + bb[2 * p];
                y[2 * p + 1] = v.y + bb[2 * p + 1];
            }
#pragma unroll
            for (int m = 0; m < 8; m++) { sum[m] += y[m]; sq[m] += y[m] * y[m]; }
            size_t row = (size_t)(tbase + rg + r * 16);
            float4* o = (float4*)(g_y3 + row * CC + cg * 8);
            o[0] = make_float4(y[0], y[1], y[2], y[3]);
            o[1] = make_float4(y[4], y[5], y[6], y[7]);
        }
    }
    __syncthreads();
#pragma unroll
    for (int m = 0; m < 8; m++) {
        atomicAdd(&sred[cg * 8 + m], sum[m]);
        atomicAdd(&sred[128 + cg * 8 + m], sq[m]);
    }
    __syncthreads();
    atomicAdd(&g_sumbuf[256 + tid], sred[tid]);   // [256:512) = c3 sum|sq
}

// ============================================================================
// K3: finalize c2 / c3 BN coefficients
// ============================================================================
__global__ void k_stats1(const float* __restrict__ gc2, const float* __restrict__ bc2,
                         const float* __restrict__ gc3, const float* __restrict__ bc3) {
    int tid = threadIdx.x;  // 256
    if (tid < 128) {
        float mean = g_sumbuf[tid] * (1.0f / NEDGE);
        float var  = g_sumbuf[128 + tid] * (1.0f / NEDGE) - mean * mean;
        float a = gc2[tid] * rsqrtf(var + EPSF);
        g_ab[tid] = a;
        g_ab[128 + tid] = bc2[tid] - mean * a;
    } else {
        int c = tid - 128;
        float mean = g_sumbuf[256 + c] * (1.0f / NTRI);
        float var  = g_sumbuf[384 + c] * (1.0f / NTRI) - mean * mean;
        float a = gc3[c] * rsqrtf(var + EPSF);
        g_ab[256 + c] = a;
        g_ab[384 + c] = bc3[c] - mean * a;
    }
}

// ============================================================================
// K4: c2 activation: g2 = sigmoid(BN(y2_f)) * tanh(BN(y2_c)), + g2 stats
// One thread per (edge, 4-col group). float4 loads/stores.
// ============================================================================
__global__ void __launch_bounds__(256) k_c2act() {
    __shared__ float sred[128];
    int tid = threadIdx.x;
    if (tid < 128) sred[tid] = 0.0f;
    __syncthreads();
    size_t i0 = (size_t)blockIdx.x * 256 + tid;
    int c = (int)(i0 & 15) * 4;
    float4 af = *(const float4*)&g_ab[c];
    float4 bf = *(const float4*)&g_ab[128 + c];
    float4 ac = *(const float4*)&g_ab[64 + c];
    float4 bc = *(const float4*)&g_ab[192 + c];
    float s[4] = {0, 0, 0, 0}, q[4] = {0, 0, 0, 0};
    size_t stride = (size_t)gridDim.x * 256;
    size_t n = (size_t)NEDGE * 16;
    for (size_t idx = i0; idx < n; idx += stride) {
        size_t e = idx >> 4;
        float4 yf = *(const float4*)&g_y2[(e << 7) + c];
        float4 yc = *(const float4*)&g_y2[(e << 7) + 64 + c];
        float4 g;
        g.x = sigmoidf_(yf.x * af.x + bf.x) * tanhf(yc.x * ac.x + bc.x);
        g.y = sigmoidf_(yf.y * af.y + bf.y) * tanhf(yc.y * ac.y + bc.y);
        g.z = sigmoidf_(yf.z * af.z + bf.z) * tanhf(yc.z * ac.z + bc.z);
        g.w = sigmoidf_(yf.w * af.w + bf.w) * tanhf(yc.w * ac.w + bc.w);
        *(float4*)&g_g2[idx << 2] = g;
        s[0] += g.x; s[1] += g.y; s[2] += g.z; s[3] += g.w;
        q[0] += g.x * g.x; q[1] += g.y * g.y; q[2] += g.z * g.z; q[3] += g.w * g.w;
    }
#pragma unroll
    for (int u = 0; u < 4; u++) {
        atomicAdd(&sred[c + u], s[u]);
        atomicAdd(&sred[64 + c + u], q[u]);
    }
    __syncthreads();
    if (tid < 128) atomicAdd(&g_sumbuf[512 + tid], sred[tid]);
}

// ============================================================================
// K5: c3 activation + segment-sum scatter: agg[iji[t]] += sigmoid*tanh
// One thread per (triplet, 4-col group); vector red.global.add
// ============================================================================
__global__ void __launch_bounds__(256) k_c3act(const int* __restrict__ iji) {
    size_t i0 = (size_t)blockIdx.x * 256 + threadIdx.x;
    int c = (int)(i0 & 15) * 4;
    float4 af = *(const float4*)&g_ab[256 + c];
    float4 bf = *(const float4*)&g_ab[384 + c];
    float4 ac = *(const float4*)&g_ab[320 + c];
    float4 bc = *(const float4*)&g_ab[448 + c];
    size_t stride = (size_t)gridDim.x * 256;
    size_t n = (size_t)NTRI * 16;
    for (size_t idx = i0; idx < n; idx += stride) {
        size_t t = idx >> 4;
        float4 yf = *(const float4*)&g_y3[(t << 7) + c];
        float4 yc = *(const float4*)&g_y3[(t << 7) + 64 + c];
        float m0 = sigmoidf_(yf.x * af.x + bf.x) * tanhf(yc.x * ac.x + bc.x);
        float m1 = sigmoidf_(yf.y * af.y + bf.y) * tanhf(yc.y * ac.y + bc.y);
        float m2 = sigmoidf_(yf.z * af.z + bf.z) * tanhf(yc.z * ac.z + bc.z);
        float m3 = sigmoidf_(yf.w * af.w + bf.w) * tanhf(yc.w * ac.w + bc.w);
        float* dst = g_agg + ((size_t)iji[t] << 6) + c;
        asm volatile("red.global.v4.f32.add [%0], {%1, %2, %3, %4};"
                     :: "l"(dst), "f"(m0), "f"(m1), "f"(m2), "f"(m3) : "memory");
    }
}

// ============================================================================
// K6a: agg column stats (float4)
// ============================================================================
__global__ void __launch_bounds__(256) k_aggstats() {
    __shared__ float sred[128];
    int tid = threadIdx.x;
    if (tid < 128) sred[tid] = 0.0f;
    __syncthreads();
    size_t i0 = (size_t)blockIdx.x * 256 + tid;
    int c = (int)(i0 & 15) * 4;
    float s[4] = {0, 0, 0, 0}, q[4] = {0, 0, 0, 0};
    size_t stride = (size_t)gridDim.x * 256;
    size_t n = (size_t)NEDGE * 16;
    for (size_t idx = i0; idx < n; idx += stride) {
        float4 v = *(const float4*)&g_agg[idx << 2];
        s[0] += v.x; s[1] += v.y; s[2] += v.z; s[3] += v.w;
        q[0] += v.x * v.x; q[1] += v.y * v.y; q[2] += v.z * v.z; q[3] += v.w * v.w;
    }
#pragma unroll
    for (int u = 0; u < 4; u++) {
        atomicAdd(&sred[c + u], s[u]);
        atomicAdd(&sred[64 + c + u], q[u]);
    }
    __syncthreads();
    if (tid < 128) atomicAdd(&g_sumbuf[640 + tid], sred[tid]);
}

// ============================================================================
// K6b: finalize g2 / agg BN coefficients
// ============================================================================
__global__ void k_stats2(const float* __restrict__ g22, const float* __restrict__ b22,
                         const float* __restrict__ g32, const float* __restrict__ b32) {
    int tid = threadIdx.x;  // 128
    if (tid < 64) {
        float mean = g_sumbuf[512 + tid] * (1.0f / NEDGE);
        float var  = g_sumbuf[576 + tid] * (1.0f / NEDGE) - mean * mean;
        float a = g22[tid] * rsqrtf(var + EPSF);
        g_ab[512 + tid] = a;
        g_ab[576 + tid] = b22[tid] - mean * a;
    } else {
        int c = tid - 64;
        float mean = g_sumbuf[640 + c] * (1.0f / NEDGE);
        float var  = g_sumbuf[704 + c] * (1.0f / NEDGE) - mean * mean;
        float a = g32[c] * rsqrtf(var + EPSF);
        g_ab[640 + c] = a;
        g_ab[704 + c] = b32[c] - mean * a;
    }
}

// ============================================================================
// K7: out = tanh(edge + BN(g2) + BN(agg))  (float4)
// ============================================================================
__global__ void __launch_bounds__(256) k_out(const float* __restrict__ edge,
                                             float* __restrict__ out) {
    size_t i0 = (size_t)blockIdx.x * 256 + threadIdx.x;
    int c = (int)(i0 & 15) * 4;
    float4 a2 = *(const float4*)&g_ab[512 + c];
    float4 b2v = *(const float4*)&g_ab[576 + c];
    float4 a3 = *(const float4*)&g_ab[640 + c];
    float4 b3v = *(const float4*)&g_ab[704 + c];
    size_t stride = (size_t)gridDim.x * 256;
    size_t n = (size_t)NEDGE * 16;
    for (size_t idx = i0; idx < n; idx += stride) {
        float4 e = *(const float4*)&edge[idx << 2];
        float4 g = *(const float4*)&g_g2[idx << 2];
        float4 a = *(const float4*)&g_agg[idx << 2];
        float4 o;
        o.x = tanhf(e.x + g.x * a2.x + b2v.x + a.x * a3.x + b3v.x);
        o.y = tanhf(e.y + g.y * a2.y + b2v.y + a.y * a3.y + b3v.y);
        o.z = tanhf(e.z + g.z * a2.z + b2v.z + a.z * a3.z + b3v.z);
        o.w = tanhf(e.w + g.w * a2.w + b2v.w + a.w * a3.w + b3v.w);
        *(float4*)&out[idx << 2] = o;
    }
}

// ============================================================================
extern "C" void kernel_launch(void* const* d_in, const int* in_sizes, int n_in,
                              void* d_out, int out_size) {
    const float* node   = (const float*)d_in[0];
    const float* edge   = (const float*)d_in[1];
    const int* vi       = (const int*)d_in[2];
    const int* vj       = (const int*)d_in[3];
    const int* idx_i    = (const int*)d_in[4];
    const int* idx_j    = (const int*)d_in[5];
    const int* idx_k    = (const int*)d_in[6];
    const int* idx_ji   = (const int*)d_in[7];
    const int* idx_kj   = (const int*)d_in[8];
    const float* W2     = (const float*)d_in[9];
    const float* b2     = (const float*)d_in[10];
    const float* W3     = (const float*)d_in[11];
    const float* b3     = (const float*)d_in[12];
    const float* gc2    = (const float*)d_in[13];
    const float* bc2    = (const float*)d_in[14];
    const float* gc3    = (const float*)d_in[15];
    const float* bc3    = (const float*)d_in[16];
    const float* g22    = (const float*)d_in[17];
    const float* b22    = (const float*)d_in[18];
    const float* g32    = (const float*)d_in[19];
    const float* b32    = (const float*)d_in[20];
    float* out = (float*)d_out;

    const int smem_k3 = (D3 * CC + 48 * 324) * (int)sizeof(float);   // 226048 B
    const int smem_k1 = (64 * CC + 64 * 72) * (int)sizeof(float);    // 51200 B
    cudaFuncSetAttribute(k_c3mm, cudaFuncAttributeMaxDynamicSharedMemorySize, smem_k3);
    cudaFuncSetAttribute(k_c2mm, cudaFuncAttributeMaxDynamicSharedMemorySize, smem_k1);

    k_zero<<<1024, 256>>>();
    k_c2mm<<<592, 256, smem_k1>>>(node, vi, vj, W2, b2);
    k_c3mm<<<148, 256, smem_k3>>>(node, edge, idx_i, idx_j, idx_k, idx_ji, idx_kj, W3, b3);
    k_stats1<<<1, 256>>>(gc2, bc2, gc3, bc3);
    k_c2act<<<512, 256>>>();
    k_c3act<<<2048, 256>>>(idx_ji);
    k_aggstats<<<512, 256>>>();
    k_stats2<<<1, 128>>>(g22, b22, g32, b32);
    k_out<<<512, 256>>>(edge, out);
}

// round 5
// speedup vs baseline: 1.0023x; 1.0023x over previous
#include <cuda_runtime.h>
#include <cstdint>
#include <math.h>

#define HN 64
#define HE 64
#define NNODE 50000
#define NEDGE 200000
#define NTRI  600000
#define CC 128          // 2*HE
#define D3 320          // 3*HN + 2*HE
#define EPSF 1e-5f

// ---------------- scratch (static device arrays; no allocation) ----------------
__device__ float g_y2[(size_t)NEDGE * CC];    // c2 pre-BN linear out (E,128)
__device__ float g_y3[(size_t)NTRI * CC];     // c3 pre-BN linear out (T,128)
__device__ float g_g2[(size_t)NEDGE * HE];    // sigmoid*tanh of c2 (E,64)
__device__ float g_agg[(size_t)NEDGE * HE];   // segment-summed msg (E,64)
// sums: [0:128) c2 sum, [128:256) c2 sq, [256:384) c3 sum, [384:512) c3 sq,
//       [512:576) g2 sum, [576:640) g2 sq, [640:704) agg sum, [704:768) agg sq
__device__ float g_sumbuf[768];
// ab: (a,b) affine coefficients per BN: y*a + b  (same layout)
__device__ float g_ab[768];

// ---------------- packed f32x2 helpers (sm_103a FFMA2 path) ----------------
__device__ __forceinline__ unsigned long long fma2(unsigned long long a,
                                                   unsigned long long b,
                                                   unsigned long long c) {
    unsigned long long d;
    asm("fma.rn.f32x2 %0, %1, %2, %3;" : "=l"(d) : "l"(a), "l"(b), "l"(c));
    return d;
}
__device__ __forceinline__ unsigned long long pack2(float lo, float hi) {
    unsigned long long d;
    asm("mov.b64 %0, {%1, %2};" : "=l"(d) : "f"(lo), "f"(hi));
    return d;
}
__device__ __forceinline__ float2 unpack2(unsigned long long v) {
    float2 r;
    asm("mov.b64 {%0, %1}, %2;" : "=f"(r.x), "=f"(r.y) : "l"(v));
    return r;
}

__device__ __forceinline__ float sigmoidf_(float x) {
    return 1.0f / (1.0f + __expf(-x));
}

// W shared-layout permutation: thread cg (0..15) owns cols cg*8..cg*8+7.
// Col c stored at ((c>>3)<<2) + (q&3) + ((q&4)<<4), q=c&7: each 16B load
// across 16 lanes is a contiguous 256B conflict-free block.
__device__ __forceinline__ int wpos(int c) {
    int q = c & 7;
    return ((c >> 3) << 2) + (q & 3) + ((q & 4) << 4);
}

// ============================================================================
// K0: zero g_agg and stat sums
// ============================================================================
__global__ void k_zero() {
    size_t i = (size_t)blockIdx.x * blockDim.x + threadIdx.x;
    size_t stride = (size_t)gridDim.x * blockDim.x;
    size_t n = (size_t)NEDGE * HE / 4;
    float4 z = make_float4(0.f, 0.f, 0.f, 0.f);
    float4* p4 = (float4*)g_agg;
    for (size_t p = i; p < n; p += stride) p4[p] = z;
    if (i < 768) g_sumbuf[i] = 0.0f;
}

// ============================================================================
// K1: c2 linear.  x = node[i]*node[j] (64), y = W2 x + b2 (128).
// 64-edge tiles, 256 threads, 4 rows/thread. FFMA2 inner loop.
// ============================================================================
__global__ void __launch_bounds__(256) k_c2mm(const float* __restrict__ node,
                                              const int* __restrict__ vi,
                                              const int* __restrict__ vj,
                                              const float* __restrict__ W2,
                                              const float* __restrict__ b2) {
    extern __shared__ __align__(16) float smem2[];
    float* sw = smem2;               // 64*128 floats (32KB)
    float* sx = smem2 + 64 * CC;     // 64*72 floats (18KB)
    __shared__ float sred[256];
    const int tid = threadIdx.x;

    for (int idx = tid; idx < 64 * 128; idx += 256) {
        int c = idx >> 6, k = idx & 63;
        sw[(k << 7) + wpos(c)] = W2[idx];
    }
    sred[tid] = 0.0f;

    const int cg = tid & 15;
    const int rg = tid >> 4;       // 0..15
    const int l8 = tid & 7;
    float bb[8];
#pragma unroll
    for (int m = 0; m < 8; m++) bb[m] = b2[cg * 8 + m];

    float sum[8], sq[8];
#pragma unroll
    for (int m = 0; m < 8; m++) { sum[m] = 0.0f; sq[m] = 0.0f; }

    const int ntiles = NEDGE / 64;
    for (int tile = blockIdx.x; tile < ntiles; tile += gridDim.x) {
        const int ebase = tile << 6;
        __syncthreads();
        // gather: 8 threads per edge, 64 edges → 2 passes
        for (int p = tid >> 3; p < 64; p += 32) {
            int e = ebase + p;
            const float4* a = (const float4*)(node + (size_t)vi[e] * HN) + l8 * 2;
            const float4* b = (const float4*)(node + (size_t)vj[e] * HN) + l8 * 2;
            float4 a0 = a[0], a1 = a[1];
            float4 b0 = b[0], b1 = b[1];
            float* dst = sx + p * 72 + l8 * 8;
            *(float4*)dst = make_float4(a0.x * b0.x, a0.y * b0.y, a0.z * b0.z, a0.w * b0.w);
            *(float4*)(dst + 4) = make_float4(a1.x * b1.x, a1.y * b1.y, a1.z * b1.z, a1.w * b1.w);
        }
        __syncthreads();

        unsigned long long acc[4][4];
#pragma unroll
        for (int r = 0; r < 4; r++)
#pragma unroll
            for (int p = 0; p < 4; p++) acc[r][p] = 0ull;
        const float* xp0 = sx + rg * 72;

#pragma unroll 2
        for (int k = 0; k < 64; k += 4) {
            float4 xv[4];
            xv[0] = *(const float4*)(xp0 + k);
            xv[1] = *(const float4*)(xp0 + 16 * 72 + k);
            xv[2] = *(const float4*)(xp0 + 32 * 72 + k);
            xv[3] = *(const float4*)(xp0 + 48 * 72 + k);
#pragma unroll
            for (int u = 0; u < 4; u++) {
                const float* wr = sw + ((k + u) << 7) + cg * 4;
                ulonglong2 wa = *(const ulonglong2*)(wr);
                ulonglong2 wb = *(const ulonglong2*)(wr + 64);
#pragma unroll
                for (int r = 0; r < 4; r++) {
                    float f = (u == 0) ? xv[r].x : (u == 1) ? xv[r].y : (u == 2) ? xv[r].z : xv[r].w;
                    unsigned long long xx = pack2(f, f);
                    acc[r][0] = fma2(xx, wa.x, acc[r][0]);
                    acc[r][1] = fma2(xx, wa.y, acc[r][1]);
                    acc[r][2] = fma2(xx, wb.x, acc[r][2]);
                    acc[r][3] = fma2(xx, wb.y, acc[r][3]);
                }
            }
        }
#pragma unroll
        for (int r = 0; r < 4; r++) {
            float y[8];
#pragma unroll
            for (int p = 0; p < 4; p++) {
                float2 v = unpack2(acc[r][p]);
                y[2 * p] = v.x + bb[2 * p];
                y[2 * p + 1] = v.y + bb[2 * p + 1];
            }
#pragma unroll
            for (int m = 0; m < 8; m++) { sum[m] += y[m]; sq[m] += y[m] * y[m]; }
            size_t row = (size_t)(ebase + rg + r * 16);
            float4* o = (float4*)(g_y2 + row * CC + cg * 8);
            o[0] = make_float4(y[0], y[1], y[2], y[3]);
            o[1] = make_float4(y[4], y[5], y[6], y[7]);
        }
    }
    __syncthreads();
#pragma unroll
    for (int m = 0; m < 8; m++) {
        atomicAdd(&sred[cg * 8 + m], sum[m]);
        atomicAdd(&sred[128 + cg * 8 + m], sq[m]);
    }
    __syncthreads();
    atomicAdd(&g_sumbuf[tid], sred[tid]);   // [0:256) = c2 sum|sq
}

// ============================================================================
// K2: c3 linear. x = concat(node[ii],node[ij],node[ik],edge[iji],edge[ikj]) (320)
// y = W3 x + b3 (128). 48-triplet tiles, 3 rows/thread, W3 resident (160KB).
// ============================================================================
__global__ void __launch_bounds__(256) k_c3mm(const float* __restrict__ node,
                                              const float* __restrict__ edge,
                                              const int* __restrict__ ii,
                                              const int* __restrict__ ij,
                                              const int* __restrict__ ik,
                                              const int* __restrict__ iji,
                                              const int* __restrict__ ikj,
                                              const float* __restrict__ W3,
                                              const float* __restrict__ b3) {
    extern __shared__ __align__(16) float smem[];
    float* sw = smem;                 // 320*128 floats (160KB)
    float* sx = smem + D3 * CC;       // 48*324 floats (62KB)
    __shared__ float sred[256];
    const int tid = threadIdx.x;

    for (int idx = tid; idx < D3 * CC; idx += 256) {
        int c = idx / D3;
        int k = idx - c * D3;
        sw[k * CC + wpos(c)] = W3[idx];
    }
    sred[tid] = 0.0f;

    const int cg = tid & 15;
    const int rg = tid >> 4;         // 0..15
    const int l8 = tid & 7;
    float bb[8];
#pragma unroll
    for (int m = 0; m < 8; m++) bb[m] = b3[cg * 8 + m];

    float sum[8], sq[8];
#pragma unroll
    for (int m = 0; m < 8; m++) { sum[m] = 0.0f; sq[m] = 0.0f; }

    const int ntiles = NTRI / 48;
    for (int tile = blockIdx.x; tile < ntiles; tile += gridDim.x) {
        const int tbase = tile * 48;
        __syncthreads();
        // gather 48 rows x 320 floats: 240 (row,seg) pairs, 8 threads per pair
        for (int p = tid >> 3; p < 240; p += 32) {
            int r = p / 5, s = p - r * 5;
            int t = tbase + r;
            const float* src;
            int gi;
            if (s == 0)      { gi = ii[t];  src = node; }
            else if (s == 1) { gi = ij[t];  src = node; }
            else if (s == 2) { gi = ik[t];  src = node; }
            else if (s == 3) { gi = iji[t]; src = edge; }
            else             { gi = ikj[t]; src = edge; }
            const float4* sp = (const float4*)(src + (size_t)gi * 64) + l8 * 2;
            float4 v0 = sp[0], v1 = sp[1];
            float* dst = sx + r * 324 + s * 64 + l8 * 8;
            *(float4*)dst = v0;
            *(float4*)(dst + 4) = v1;
        }
        __syncthreads();

        unsigned long long acc[3][4];
#pragma unroll
        for (int r = 0; r < 3; r++)
#pragma unroll
            for (int p = 0; p < 4; p++) acc[r][p] = 0ull;
        const float* xp0 = sx + rg * 324;

#pragma unroll 2
        for (int k = 0; k < D3; k += 4) {
            float4 xv[3];
            xv[0] = *(const float4*)(xp0 + k);
            xv[1] = *(const float4*)(xp0 + 16 * 324 + k);
            xv[2] = *(const float4*)(xp0 + 32 * 324 + k);
#pragma unroll
            for (int u = 0; u < 4; u++) {
                const float* wr = sw + (k + u) * CC + cg * 4;
                ulonglong2 wa = *(const ulonglong2*)(wr);
                ulonglong2 wb = *(const ulonglong2*)(wr + 64);
#pragma unroll
                for (int r = 0; r < 3; r++) {
                    float f = (u == 0) ? xv[r].x : (u == 1) ? xv[r].y : (u == 2) ? xv[r].z : xv[r].w;
                    unsigned long long xx = pack2(f, f);
                    acc[r][0] = fma2(xx, wa.x, acc[r][0]);
                    acc[r][1] = fma2(xx, wa.y, acc[r][1]);
                    acc[r][2] = fma2(xx, wb.x, acc[r][2]);
                    acc[r][3] = fma2(xx, wb.y, acc[r][3]);
                }
            }
        }
#pragma unroll
        for (int r = 0; r < 3; r++) {
            float y[8];
#pragma unroll
            for (int p = 0; p < 4; p++) {
                float2 v = unpack2(acc[r][p]);
                y[2 * p] = v.x + bb[2 * p];
                y[2 * p + 1] = v.y + bb[2 * p + 1];
            }
#pragma unroll
            for (int m = 0; m < 8; m++) { sum[m] += y[m]; sq[m] += y[m] * y[m]; }
            size_t row = (size_t)(tbase + rg + r * 16);
            float4* o = (float4*)(g_y3 + row * CC + cg * 8);
            o[0] = make_float4(y[0], y[1], y[2], y[3]);
            o[1] = make_float4(y[4], y[5], y[6], y[7]);
        }
    }
    __syncthreads();
#pragma unroll
    for (int m = 0; m < 8; m++) {
        atomicAdd(&sred[cg * 8 + m], sum[m]);
        atomicAdd(&sred[128 + cg * 8 + m], sq[m]);
    }
    __syncthreads();
    atomicAdd(&g_sumbuf[256 + tid], sred[tid]);   // [256:512) = c3 sum|sq
}

// ============================================================================
// K3: finalize c2 / c3 BN coefficients
// ============================================================================
__global__ void k_stats1(const float* __restrict__ gc2, const float* __restrict__ bc2,
                         const float* __restrict__ gc3, const float* __restrict__ bc3) {
    int tid = threadIdx.x;  // 256
    if (tid < 128) {
        float mean = g_sumbuf[tid] * (1.0f / NEDGE);
        float var  = g_sumbuf[128 + tid] * (1.0f / NEDGE) - mean * mean;
        float a = gc2[tid] * rsqrtf(var + EPSF);
        g_ab[tid] = a;
        g_ab[128 + tid] = bc2[tid] - mean * a;
    } else {
        int c = tid - 128;
        float mean = g_sumbuf[256 + c] * (1.0f / NTRI);
        float var  = g_sumbuf[384 + c] * (1.0f / NTRI) - mean * mean;
        float a = gc3[c] * rsqrtf(var + EPSF);
        g_ab[256 + c] = a;
        g_ab[384 + c] = bc3[c] - mean * a;
    }
}

// ============================================================================
// K4: c2 activation: g2 = sigmoid(BN(y2_f)) * tanh(BN(y2_c)), + g2 stats
// One thread per (edge, 4-col group). float4 loads/stores.
// ============================================================================
__global__ void __launch_bounds__(256) k_c2act() {
    __shared__ float sred[128];
    int tid = threadIdx.x;
    if (tid < 128) sred[tid] = 0.0f;
    __syncthreads();
    size_t i0 = (size_t)blockIdx.x * 256 + tid;
    int c = (int)(i0 & 15) * 4;
    float4 af = *(const float4*)&g_ab[c];
    float4 bf = *(const float4*)&g_ab[128 + c];
    float4 ac = *(const float4*)&g_ab[64 + c];
    float4 bc = *(const float4*)&g_ab[192 + c];
    float s[4] = {0, 0, 0, 0}, q[4] = {0, 0, 0, 0};
    size_t stride = (size_t)gridDim.x * 256;
    size_t n = (size_t)NEDGE * 16;
    for (size_t idx = i0; idx < n; idx += stride) {
        size_t e = idx >> 4;
        float4 yf = *(const float4*)&g_y2[(e << 7) + c];
        float4 yc = *(const float4*)&g_y2[(e << 7) + 64 + c];
        float4 g;
        g.x = sigmoidf_(yf.x * af.x + bf.x) * tanhf(yc.x * ac.x + bc.x);
        g.y = sigmoidf_(yf.y * af.y + bf.y) * tanhf(yc.y * ac.y + bc.y);
        g.z = sigmoidf_(yf.z * af.z + bf.z) * tanhf(yc.z * ac.z + bc.z);
        g.w = sigmoidf_(yf.w * af.w + bf.w) * tanhf(yc.w * ac.w + bc.w);
        *(float4*)&g_g2[idx << 2] = g;
        s[0] += g.x; s[1] += g.y; s[2] += g.z; s[3] += g.w;
        q[0] += g.x * g.x; q[1] += g.y * g.y; q[2] += g.z * g.z; q[3] += g.w * g.w;
    }
#pragma unroll
    for (int u = 0; u < 4; u++) {
        atomicAdd(&sred[c + u], s[u]);
        atomicAdd(&sred[64 + c + u], q[u]);
    }
    __syncthreads();
    if (tid < 128) atomicAdd(&g_sumbuf[512 + tid], sred[tid]);
}

// ============================================================================
// K5: c3 activation + segment-sum scatter: agg[iji[t]] += sigmoid*tanh
// One thread per (triplet, 4-col group); vector red.global.add
// ============================================================================
__global__ void __launch_bounds__(256) k_c3act(const int* __restrict__ iji) {
    size_t i0 = (size_t)blockIdx.x * 256 + threadIdx.x;
    int c = (int)(i0 & 15) * 4;
    float4 af = *(const float4*)&g_ab[256 + c];
    float4 bf = *(const float4*)&g_ab[384 + c];
    float4 ac = *(const float4*)&g_ab[320 + c];
    float4 bc = *(const float4*)&g_ab[448 + c];
    size_t stride = (size_t)gridDim.x * 256;
    size_t n = (size_t)NTRI * 16;
    for (size_t idx = i0; idx < n; idx += stride) {
        size_t t = idx >> 4;
        float4 yf = *(const float4*)&g_y3[(t << 7) + c];
        float4 yc = *(const float4*)&g_y3[(t << 7) + 64 + c];
        float m0 = sigmoidf_(yf.x * af.x + bf.x) * tanhf(yc.x * ac.x + bc.x);
        float m1 = sigmoidf_(yf.y * af.y + bf.y) * tanhf(yc.y * ac.y + bc.y);
        float m2 = sigmoidf_(yf.z * af.z + bf.z) * tanhf(yc.z * ac.z + bc.z);
        float m3 = sigmoidf_(yf.w * af.w + bf.w) * tanhf(yc.w * ac.w + bc.w);
        float* dst = g_agg + ((size_t)iji[t] << 6) + c;
        asm volatile("red.global.v4.f32.add [%0], {%1, %2, %3, %4};"
                     :: "l"(dst), "f"(m0), "f"(m1), "f"(m2), "f"(m3) : "memory");
    }
}

// ============================================================================
// K6a: agg column stats (float4)
// ============================================================================
__global__ void __launch_bounds__(256) k_aggstats() {
    __shared__ float sred[128];
    int tid = threadIdx.x;
    if (tid < 128) sred[tid] = 0.0f;
    __syncthreads();
    size_t i0 = (size_t)blockIdx.x * 256 + tid;
    int c = (int)(i0 & 15) * 4;
    float s[4] = {0, 0, 0, 0}, q[4] = {0, 0, 0, 0};
    size_t stride = (size_t)gridDim.x * 256;
    size_t n = (size_t)NEDGE * 16;
    for (size_t idx = i0; idx < n; idx += stride) {
        float4 v = *(const float4*)&g_agg[idx << 2];
        s[0] += v.x; s[1] += v.y; s[2] += v.z; s[3] += v.w;
        q[0] += v.x * v.x; q[1] += v.y * v.y; q[2] += v.z * v.z; q[3] += v.w * v.w;
    }
#pragma unroll
    for (int u = 0; u < 4; u++) {
        atomicAdd(&sred[c + u], s[u]);
        atomicAdd(&sred[64 + c + u], q[u]);
    }
    __syncthreads();
    if (tid < 128) atomicAdd(&g_sumbuf[640 + tid], sred[tid]);
}

// ============================================================================
// K6b: finalize g2 / agg BN coefficients
// ============================================================================
__global__ void k_stats2(const float* __restrict__ g22, const float* __restrict__ b22,
                         const float* __restrict__ g32, const float* __restrict__ b32) {
    int tid = threadIdx.x;  // 128
    if (tid < 64) {
        float mean = g_sumbuf[512 + tid] * (1.0f / NEDGE);
        float var  = g_sumbuf[576 + tid] * (1.0f / NEDGE) - mean * mean;
        float a = g22[tid] * rsqrtf(var + EPSF);
        g_ab[512 + tid] = a;
        g_ab[576 + tid] = b22[tid] - mean * a;
    } else {
        int c = tid - 64;
        float mean = g_sumbuf[640 + c] * (1.0f / NEDGE);
        float var  = g_sumbuf[704 + c] * (1.0f / NEDGE) - mean * mean;
        float a = g32[c] * rsqrtf(var + EPSF);
        g_ab[640 + c] = a;
        g_ab[704 + c] = b32[c] - mean * a;
    }
}

// ============================================================================
// K7: out = tanh(edge + BN(g2) + BN(agg))  (float4)
// ============================================================================
__global__ void __launch_bounds__(256) k_out(const float* __restrict__ edge,
                                             float* __restrict__ out) {
    size_t i0 = (size_t)blockIdx.x * 256 + threadIdx.x;
    int c = (int)(i0 & 15) * 4;
    float4 a2 = *(const float4*)&g_ab[512 + c];
    float4 b2v = *(const float4*)&g_ab[576 + c];
    float4 a3 = *(const float4*)&g_ab[640 + c];
    float4 b3v = *(const float4*)&g_ab[704 + c];
    size_t stride = (size_t)gridDim.x * 256;
    size_t n = (size_t)NEDGE * 16;
    for (size_t idx = i0; idx < n; idx += stride) {
        float4 e = *(const float4*)&edge[idx << 2];
        float4 g = *(const float4*)&g_g2[idx << 2];
        float4 a = *(const float4*)&g_agg[idx << 2];
        float4 o;
        o.x = tanhf(e.x + g.x * a2.x + b2v.x + a.x * a3.x + b3v.x);
        o.y = tanhf(e.y + g.y * a2.y + b2v.y + a.y * a3.y + b3v.y);
        o.z = tanhf(e.z + g.z * a2.z + b2v.z + a.z * a3.z + b3v.z);
        o.w = tanhf(e.w + g.w * a2.w + b2v.w + a.w * a3.w + b3v.w);
        *(float4*)&out[idx << 2] = o;
    }
}

// ============================================================================
extern "C" void kernel_launch(void* const* d_in, const int* in_sizes, int n_in,
                              void* d_out, int out_size) {
    const float* node   = (const float*)d_in[0];
    const float* edge   = (const float*)d_in[1];
    const int* vi       = (const int*)d_in[2];
    const int* vj       = (const int*)d_in[3];
    const int* idx_i    = (const int*)d_in[4];
    const int* idx_j    = (const int*)d_in[5];
    const int* idx_k    = (const int*)d_in[6];
    const int* idx_ji   = (const int*)d_in[7];
    const int* idx_kj   = (const int*)d_in[8];
    const float* W2     = (const float*)d_in[9];
    const float* b2     = (const float*)d_in[10];
    const float* W3     = (const float*)d_in[11];
    const float* b3     = (const float*)d_in[12];
    const float* gc2    = (const float*)d_in[13];
    const float* bc2    = (const float*)d_in[14];
    const float* gc3    = (const float*)d_in[15];
    const float* bc3    = (const float*)d_in[16];
    const float* g22    = (const float*)d_in[17];
    const float* b22    = (const float*)d_in[18];
    const float* g32    = (const float*)d_in[19];
    const float* b32    = (const float*)d_in[20];
    float* out = (float*)d_out;

    const int smem_k3 = (D3 * CC + 48 * 324) * (int)sizeof(float);   // 226048 B
    const int smem_k1 = (64 * CC + 64 * 72) * (int)sizeof(float);    // 51200 B
    cudaFuncSetAttribute(k_c3mm, cudaFuncAttributeMaxDynamicSharedMemorySize, smem_k3);
    cudaFuncSetAttribute(k_c2mm, cudaFuncAttributeMaxDynamicSharedMemorySize, smem_k1);

    k_zero<<<1024, 256>>>();
    k_c2mm<<<592, 256, smem_k1>>>(node, vi, vj, W2, b2);
    k_c3mm<<<148, 256, smem_k3>>>(node, edge, idx_i, idx_j, idx_k, idx_ji, idx_kj, W3, b3);
    k_stats1<<<1, 256>>>(gc2, bc2, gc3, bc3);
    k_c2act<<<512, 256>>>();
    k_c3act<<<2048, 256>>>(idx_ji);
    k_aggstats<<<512, 256>>>();
    k_stats2<<<1, 128>>>(g22, b22, g32, b32);
    k_out<<<512, 256>>>(edge, out);
}

// round 7
// speedup vs baseline: 2.1522x; 2.1473x over previous
#include <cuda_runtime.h>
#include <cuda_bf16.h>
#include <cstdint>
#include <math.h>

#define HN 64
#define HE 64
#define NEDGE 200000
#define NTRI  600000
#define CC 128
#define D3 320
#define EPSF 1e-5f
#define TILE_M 128
#define NT_TILES ((NTRI + TILE_M - 1) / TILE_M)

// ---------------- scratch ----------------
__device__ float g_y2[(size_t)NEDGE * CC];
__device__ float g_y3[(size_t)NTRI * CC];
__device__ float g_g2[(size_t)NEDGE * HE];
__device__ float g_agg[(size_t)NEDGE * HE];
__device__ unsigned short g_wbh[128 * 320];   // W3 hi bf16, panelized+swizzled
__device__ unsigned short g_wbl[128 * 320];   // W3 lo bf16
__device__ float g_sumbuf[768];
__device__ float g_ab[768];

// ---------------- helpers ----------------
__device__ __forceinline__ unsigned long long fma2(unsigned long long a, unsigned long long b, unsigned long long c) {
    unsigned long long d;
    asm("fma.rn.f32x2 %0, %1, %2, %3;" : "=l"(d) : "l"(a), "l"(b), "l"(c));
    return d;
}
__device__ __forceinline__ unsigned long long pack2(float lo, float hi) {
    unsigned long long d;
    asm("mov.b64 %0, {%1, %2};" : "=l"(d) : "f"(lo), "f"(hi));
    return d;
}
__device__ __forceinline__ float2 unpack2(unsigned long long v) {
    float2 r;
    asm("mov.b64 {%0, %1}, %2;" : "=f"(r.x), "=f"(r.y) : "l"(v));
    return r;
}
__device__ __forceinline__ float sigmoidf_(float x) { return 1.0f / (1.0f + __expf(-x)); }
__device__ __forceinline__ int wpos(int c) { int q = c & 7; return ((c >> 3) << 2) + (q & 3) + ((q & 4) << 4); }

__device__ __forceinline__ uint32_t smem_u32(const void* p) {
    uint32_t a;
    asm("{ .reg .u64 t; cvta.to.shared.u64 t, %1; cvt.u32.u64 %0, t; }" : "=r"(a) : "l"(p));
    return a;
}
__device__ __forceinline__ uint32_t bfpack(float f0, float f1) {   // f0 -> low half
    uint32_t r;
    asm("cvt.rn.bf16x2.f32 %0, %1, %2;" : "=r"(r) : "f"(f1), "f"(f0));
    return r;
}
__device__ __forceinline__ void cvt_pair(float f0, float f1, uint32_t& h, uint32_t& l) {
    h = bfpack(f0, f1);
    float r0 = f0 - __uint_as_float((h & 0xFFFFu) << 16);
    float r1 = f1 - __uint_as_float(h & 0xFFFF0000u);
    l = bfpack(r0, r1);
}
__device__ __forceinline__ void ldsm_x4(uint32_t addr, uint32_t* r) {
    asm volatile("ldmatrix.sync.aligned.m8n8.x4.shared.b16 {%0,%1,%2,%3}, [%4];"
        : "=r"(r[0]), "=r"(r[1]), "=r"(r[2]), "=r"(r[3]) : "r"(addr));
}
__device__ __forceinline__ void mma_bf16(float* c, const uint32_t* a, const uint32_t* b) {
    asm volatile("mma.sync.aligned.m16n8k16.row.col.f32.bf16.bf16.f32 "
        "{%0,%1,%2,%3}, {%4,%5,%6,%7}, {%8,%9}, {%0,%1,%2,%3};"
        : "+f"(c[0]), "+f"(c[1]), "+f"(c[2]), "+f"(c[3])
        : "r"(a[0]), "r"(a[1]), "r"(a[2]), "r"(a[3]), "r"(b[0]), "r"(b[1]));
}
// A fragment ldmatrix address (M x K image, 128B rows, SW128)
__device__ __forceinline__ uint32_t a_addr(uint32_t base, int r0, int k0, int lane) {
    int row = r0 + (lane & 15);
    int kk = k0 + ((lane >> 4) << 3);
    return base + row * 128 + ((kk * 2) ^ ((row & 7) << 4));
}
// B fragment ldmatrix address (N x K image, covers 2 n8-tiles)
__device__ __forceinline__ uint32_t b_addr(uint32_t base, int n0, int k0, int lane) {
    int row = n0 + (lane & 7) + ((lane >> 4) << 3);
    int kk = k0 + (((lane >> 3) & 1) << 3);
    return base + row * 128 + ((kk * 2) ^ ((row & 7) << 4));
}

// c3 SMEM layout: W panels hi [0,81920), lo [81920,163840); A bufs at 163840
#define SW_A 163840
#define SMEM_C3 (SW_A + 65536)   // 229376 B

// ============================================================================
__global__ void k_zero() {
    size_t i = (size_t)blockIdx.x * blockDim.x + threadIdx.x;
    size_t stride = (size_t)gridDim.x * blockDim.x;
    size_t n = (size_t)NEDGE * HE / 4;
    float4 z = make_float4(0.f, 0.f, 0.f, 0.f);
    float4* p4 = (float4*)g_agg;
    for (size_t p = i; p < n; p += stride) p4[p] = z;
    if (i < 768) g_sumbuf[i] = 0.0f;
}

// build W3 bf16 hi/lo panelized swizzled images: panel p = k>>6
__global__ void k_prepw(const float* __restrict__ W3) {
    int idx = blockIdx.x * 256 + threadIdx.x;
    if (idx >= 128 * 320) return;
    int n = idx / 320, k = idx - n * 320;
    float w = W3[idx];
    __nv_bfloat16 hb = __float2bfloat16_rn(w);
    __nv_bfloat16 lb = __float2bfloat16_rn(w - __bfloat162float(hb));
    int p = k >> 6, kk = k & 63;
    uint32_t byte = (uint32_t)p * 16384u + (uint32_t)n * 128u + (uint32_t)((kk * 2) ^ ((n & 7) << 4));
    g_wbh[byte >> 1] = __bfloat16_as_ushort(hb);
    g_wbl[byte >> 1] = __bfloat16_as_ushort(lb);
}

// ============================================================================
// K1: c2 linear (FFMA2 path, unchanged — known good)
// ============================================================================
__global__ void __launch_bounds__(256) k_c2mm(const float* __restrict__ node,
                                              const int* __restrict__ vi,
                                              const int* __restrict__ vj,
                                              const float* __restrict__ W2,
                                              const float* __restrict__ b2) {
    extern __shared__ __align__(16) float smem2[];
    float* sw = smem2;
    float* sx = smem2 + 64 * CC;
    __shared__ float sred[256];
    const int tid = threadIdx.x;
    for (int idx = tid; idx < 64 * 128; idx += 256) {
        int c = idx >> 6, k = idx & 63;
        sw[(k << 7) + wpos(c)] = W2[idx];
    }
    sred[tid] = 0.0f;
    const int cg = tid & 15, rg = tid >> 4, l8 = tid & 7;
    float bb[8];
#pragma unroll
    for (int m = 0; m < 8; m++) bb[m] = b2[cg * 8 + m];
    float sum[8], sq[8];
#pragma unroll
    for (int m = 0; m < 8; m++) { sum[m] = 0.0f; sq[m] = 0.0f; }

    const int ntiles = NEDGE / 64;
    for (int tile = blockIdx.x; tile < ntiles; tile += gridDim.x) {
        const int ebase = tile << 6;
        __syncthreads();
        for (int p = tid >> 3; p < 64; p += 32) {
            int e = ebase + p;
            const float4* a = (const float4*)(node + (size_t)vi[e] * HN) + l8 * 2;
            const float4* b = (const float4*)(node + (size_t)vj[e] * HN) + l8 * 2;
            float4 a0 = a[0], a1 = a[1], b0 = b[0], b1 = b[1];
            float* dst = sx + p * 72 + l8 * 8;
            *(float4*)dst = make_float4(a0.x * b0.x, a0.y * b0.y, a0.z * b0.z, a0.w * b0.w);
            *(float4*)(dst + 4) = make_float4(a1.x * b1.x, a1.y * b1.y, a1.z * b1.z, a1.w * b1.w);
        }
        __syncthreads();
        unsigned long long acc[4][4];
#pragma unroll
        for (int r = 0; r < 4; r++)
#pragma unroll
            for (int p = 0; p < 4; p++) acc[r][p] = 0ull;
        const float* xp0 = sx + rg * 72;
#pragma unroll 2
        for (int k = 0; k < 64; k += 4) {
            float4 xv[4];
            xv[0] = *(const float4*)(xp0 + k);
            xv[1] = *(const float4*)(xp0 + 16 * 72 + k);
            xv[2] = *(const float4*)(xp0 + 32 * 72 + k);
            xv[3] = *(const float4*)(xp0 + 48 * 72 + k);
#pragma unroll
            for (int u = 0; u < 4; u++) {
                const float* wr = sw + ((k + u) << 7) + cg * 4;
                ulonglong2 wa = *(const ulonglong2*)(wr);
                ulonglong2 wb = *(const ulonglong2*)(wr + 64);
#pragma unroll
                for (int r = 0; r < 4; r++) {
                    float f = (u == 0) ? xv[r].x : (u == 1) ? xv[r].y : (u == 2) ? xv[r].z : xv[r].w;
                    unsigned long long xx = pack2(f, f);
                    acc[r][0] = fma2(xx, wa.x, acc[r][0]);
                    acc[r][1] = fma2(xx, wa.y, acc[r][1]);
                    acc[r][2] = fma2(xx, wb.x, acc[r][2]);
                    acc[r][3] = fma2(xx, wb.y, acc[r][3]);
                }
            }
        }
#pragma unroll
        for (int r = 0; r < 4; r++) {
            float y[8];
#pragma unroll
            for (int p = 0; p < 4; p++) {
                float2 v = unpack2(acc[r][p]);
                y[2 * p] = v.x + bb[2 * p];
                y[2 * p + 1] = v.y + bb[2 * p + 1];
            }
#pragma unroll
            for (int m = 0; m < 8; m++) { sum[m] += y[m]; sq[m] += y[m] * y[m]; }
            size_t row = (size_t)(ebase + rg + r * 16);
            float4* o = (float4*)(g_y2 + row * CC + cg * 8);
            o[0] = make_float4(y[0], y[1], y[2], y[3]);
            o[1] = make_float4(y[4], y[5], y[6], y[7]);
        }
    }
    __syncthreads();
#pragma unroll
    for (int m = 0; m < 8; m++) {
        atomicAdd(&sred[cg * 8 + m], sum[m]);
        atomicAdd(&sred[128 + cg * 8 + m], sq[m]);
    }
    __syncthreads();
    atomicAdd(&g_sumbuf[tid], sred[tid]);
}

// ============================================================================
// K2: c3 linear via mma.sync bf16 (2-split, 3 terms). y3 = x @ W3^T (no bias).
// ============================================================================
__device__ __forceinline__ void gather_regs(const float* __restrict__ src,
                                            const int* __restrict__ idx,
                                            int tbase, int tid, float4* v) {
    int r = tid >> 1, half = tid & 1;
    int t = tbase + r;
    if (t < NTRI) {
        const float4* sp = (const float4*)(src + (size_t)idx[t] * 64) + half * 8;
#pragma unroll
        for (int i = 0; i < 8; i++) v[i] = sp[i];
    } else {
#pragma unroll
        for (int i = 0; i < 8; i++) v[i] = make_float4(0.f, 0.f, 0.f, 0.f);
    }
}
__device__ __forceinline__ void cvt_store(const float4* v, char* buf, int tid) {
    int r = tid >> 1, half = tid & 1;
    int swm = (r & 7) << 4;
#pragma unroll
    for (int i = 0; i < 8; i++) {
        uint32_t h0, l0, h1, l1;
        cvt_pair(v[i].x, v[i].y, h0, l0);
        cvt_pair(v[i].z, v[i].w, h1, l1);
        int off = r * 128 + ((half * 64 + i * 8) ^ swm);
        *(uint2*)(buf + off) = make_uint2(h0, h1);
        *(uint2*)(buf + 16384 + off) = make_uint2(l0, l1);
    }
}
__device__ __forceinline__ void mma_panel(uint32_t abase, uint32_t wbh, uint32_t wbl,
                                          int wm, int wn, int lane, float acc[2][8][4]) {
    uint32_t abl = abase + 16384;
#pragma unroll
    for (int ks = 0; ks < 4; ks++) {
        int k0 = ks * 16;
        uint32_t ah[2][4], al[2][4];
        ldsm_x4(a_addr(abase, wm * 32, k0, lane), ah[0]);
        ldsm_x4(a_addr(abase, wm * 32 + 16, k0, lane), ah[1]);
        ldsm_x4(a_addr(abl, wm * 32, k0, lane), al[0]);
        ldsm_x4(a_addr(abl, wm * 32 + 16, k0, lane), al[1]);
        uint32_t bh[4][4], bl[4][4];
#pragma unroll
        for (int g = 0; g < 4; g++) {
            ldsm_x4(b_addr(wbh, wn * 64 + g * 16, k0, lane), bh[g]);
            ldsm_x4(b_addr(wbl, wn * 64 + g * 16, k0, lane), bl[g]);
        }
#pragma unroll
        for (int mt = 0; mt < 2; mt++)
#pragma unroll
            for (int g = 0; g < 4; g++) {
                mma_bf16(acc[mt][2 * g],     ah[mt], &bh[g][0]);
                mma_bf16(acc[mt][2 * g + 1], ah[mt], &bh[g][2]);
                mma_bf16(acc[mt][2 * g],     ah[mt], &bl[g][0]);
                mma_bf16(acc[mt][2 * g + 1], ah[mt], &bl[g][2]);
                mma_bf16(acc[mt][2 * g],     al[mt], &bh[g][0]);
                mma_bf16(acc[mt][2 * g + 1], al[mt], &bh[g][2]);
            }
    }
}

__global__ void __launch_bounds__(256, 1) k_c3mm(const float* __restrict__ node,
                                                 const float* __restrict__ edge,
                                                 const int* __restrict__ ii,
                                                 const int* __restrict__ ij,
                                                 const int* __restrict__ ik,
                                                 const int* __restrict__ iji,
                                                 const int* __restrict__ ikj) {
    extern __shared__ __align__(128) char smal[];
    const uint32_t sbal = smem_u32(smal);
    const int tid = threadIdx.x;
    const int wid = tid >> 5, lane = tid & 31;
    const int wm = wid >> 1, wn = wid & 1;

    // W3 images -> SMEM (163840 B)
    {
        const uint4* srch = (const uint4*)g_wbh;
        const uint4* srcl = (const uint4*)g_wbl;
        uint4* dsth = (uint4*)smal;
        uint4* dstl = (uint4*)(smal + 81920);
        for (int i = tid; i < 5120; i += 256) { dsth[i] = srch[i]; dstl[i] = srcl[i]; }
    }
    __syncthreads();

    const float* srcs[5] = {node, node, node, edge, edge};
    const int* idxs[5] = {ii, ij, ik, iji, ikj};

    for (int tile = blockIdx.x; tile < NT_TILES; tile += gridDim.x) {
        const int tbase = tile * TILE_M;
        float acc[2][8][4];
#pragma unroll
        for (int mt = 0; mt < 2; mt++)
#pragma unroll
            for (int nt = 0; nt < 8; nt++)
#pragma unroll
                for (int u = 0; u < 4; u++) acc[mt][nt][u] = 0.0f;

        float4 v[8];
        gather_regs(srcs[0], idxs[0], tbase, tid, v);
        cvt_store(v, smal + SW_A, tid);
        __syncthreads();
#pragma unroll
        for (int p = 0; p < 5; p++) {
            if (p < 4) gather_regs(srcs[p + 1], idxs[p + 1], tbase, tid, v);
            mma_panel(sbal + SW_A + (uint32_t)(p & 1) * 32768u,
                      sbal + (uint32_t)p * 16384u,
                      sbal + 81920u + (uint32_t)p * 16384u, wm, wn, lane, acc);
            if (p < 4) cvt_store(v, smal + SW_A + ((p + 1) & 1) * 32768, tid);
            __syncthreads();
        }
        // epilogue
        int lr = lane >> 2, lq = lane & 3;
#pragma unroll
        for (int mt = 0; mt < 2; mt++) {
            int gr = tbase + wm * 32 + mt * 16 + lr;
#pragma unroll
            for (int nt = 0; nt < 8; nt++) {
                int col = wn * 64 + nt * 8 + lq * 2;
                if (gr < NTRI)
                    *(float2*)&g_y3[(size_t)gr * CC + col] = make_float2(acc[mt][nt][0], acc[mt][nt][1]);
                if (gr + 8 < NTRI)
                    *(float2*)&g_y3[(size_t)(gr + 8) * CC + col] = make_float2(acc[mt][nt][2], acc[mt][nt][3]);
            }
        }
    }
}

// ============================================================================
// K2b: y3 column stats (bias-free; b3 cancels in BN)
// ============================================================================
__global__ void __launch_bounds__(256) k_y3stats() {
    __shared__ float sred[256];
    int tid = threadIdx.x;
    sred[tid] = 0.0f;
    __syncthreads();
    size_t i0 = (size_t)blockIdx.x * 256 + tid;
    int c = (int)(i0 & 31) * 4;
    float s[4] = {0, 0, 0, 0}, q[4] = {0, 0, 0, 0};
    size_t stride = (size_t)gridDim.x * 256;
    size_t n = (size_t)NTRI * 32;
    for (size_t idx = i0; idx < n; idx += stride) {
        float4 v = *(const float4*)&g_y3[idx << 2];
        s[0] += v.x; s[1] += v.y; s[2] += v.z; s[3] += v.w;
        q[0] += v.x * v.x; q[1] += v.y * v.y; q[2] += v.z * v.z; q[3] += v.w * v.w;
    }
#pragma unroll
    for (int u = 0; u < 4; u++) {
        atomicAdd(&sred[c + u], s[u]);
        atomicAdd(&sred[128 + c + u], q[u]);
    }
    __syncthreads();
    atomicAdd(&g_sumbuf[256 + tid], sred[tid]);
}

// ============================================================================
__global__ void k_stats1(const float* __restrict__ gc2, const float* __restrict__ bc2,
                         const float* __restrict__ gc3, const float* __restrict__ bc3) {
    int tid = threadIdx.x;  // 256
    if (tid < 128) {
        float mean = g_sumbuf[tid] * (1.0f / NEDGE);
        float var  = g_sumbuf[128 + tid] * (1.0f / NEDGE) - mean * mean;
        float a = gc2[tid] * rsqrtf(var + EPSF);
        g_ab[tid] = a;
        g_ab[128 + tid] = bc2[tid] - mean * a;
    } else {
        int c = tid - 128;
        float mean = g_sumbuf[256 + c] * (1.0f / NTRI);
        float var  = g_sumbuf[384 + c] * (1.0f / NTRI) - mean * mean;
        float a = gc3[c] * rsqrtf(var + EPSF);
        g_ab[256 + c] = a;
        g_ab[384 + c] = bc3[c] - mean * a;
    }
}

// ============================================================================
__global__ void __launch_bounds__(256) k_c2act() {
    __shared__ float sred[128];
    int tid = threadIdx.x;
    if (tid < 128) sred[tid] = 0.0f;
    __syncthreads();
    size_t i0 = (size_t)blockIdx.x * 256 + tid;
    int c = (int)(i0 & 15) * 4;
    float4 af = *(const float4*)&g_ab[c];
    float4 bf = *(const float4*)&g_ab[128 + c];
    float4 ac = *(const float4*)&g_ab[64 + c];
    float4 bc = *(const float4*)&g_ab[192 + c];
    float s[4] = {0, 0, 0, 0}, q[4] = {0, 0, 0, 0};
    size_t stride = (size_t)gridDim.x * 256;
    size_t n = (size_t)NEDGE * 16;
    for (size_t idx = i0; idx < n; idx += stride) {
        size_t e = idx >> 4;
        float4 yf = *(const float4*)&g_y2[(e << 7) + c];
        float4 yc = *(const float4*)&g_y2[(e << 7) + 64 + c];
        float4 g;
        g.x = sigmoidf_(yf.x * af.x + bf.x) * tanhf(yc.x * ac.x + bc.x);
        g.y = sigmoidf_(yf.y * af.y + bf.y) * tanhf(yc.y * ac.y + bc.y);
        g.z = sigmoidf_(yf.z * af.z + bf.z) * tanhf(yc.z * ac.z + bc.z);
        g.w = sigmoidf_(yf.w * af.w + bf.w) * tanhf(yc.w * ac.w + bc.w);
        *(float4*)&g_g2[idx << 2] = g;
        s[0] += g.x; s[1] += g.y; s[2] += g.z; s[3] += g.w;
        q[0] += g.x * g.x; q[1] += g.y * g.y; q[2] += g.z * g.z; q[3] += g.w * g.w;
    }
#pragma unroll
    for (int u = 0; u < 4; u++) {
        atomicAdd(&sred[c + u], s[u]);
        atomicAdd(&sred[64 + c + u], q[u]);
    }
    __syncthreads();
    if (tid < 128) atomicAdd(&g_sumbuf[512 + tid], sred[tid]);
}

// ============================================================================
__global__ void __launch_bounds__(256) k_c3act(const int* __restrict__ iji) {
    size_t i0 = (size_t)blockIdx.x * 256 + threadIdx.x;
    int c = (int)(i0 & 15) * 4;
    float4 af = *(const float4*)&g_ab[256 + c];
    float4 bf = *(const float4*)&g_ab[384 + c];
    float4 ac = *(const float4*)&g_ab[320 + c];
    float4 bc = *(const float4*)&g_ab[448 + c];
    size_t stride = (size_t)gridDim.x * 256;
    size_t n = (size_t)NTRI * 16;
    for (size_t idx = i0; idx < n; idx += stride) {
        size_t t = idx >> 4;
        float4 yf = *(const float4*)&g_y3[(t << 7) + c];
        float4 yc = *(const float4*)&g_y3[(t << 7) + 64 + c];
        float m0 = sigmoidf_(yf.x * af.x + bf.x) * tanhf(yc.x * ac.x + bc.x);
        float m1 = sigmoidf_(yf.y * af.y + bf.y) * tanhf(yc.y * ac.y + bc.y);
        float m2 = sigmoidf_(yf.z * af.z + bf.z) * tanhf(yc.z * ac.z + bc.z);
        float m3 = sigmoidf_(yf.w * af.w + bf.w) * tanhf(yc.w * ac.w + bc.w);
        float* dst = g_agg + ((size_t)iji[t] << 6) + c;
        asm volatile("red.global.v4.f32.add [%0], {%1, %2, %3, %4};"
                     :: "l"(dst), "f"(m0), "f"(m1), "f"(m2), "f"(m3) : "memory");
    }
}

// ============================================================================
__global__ void __launch_bounds__(256) k_aggstats() {
    __shared__ float sred[128];
    int tid = threadIdx.x;
    if (tid < 128) sred[tid] = 0.0f;
    __syncthreads();
    size_t i0 = (size_t)blockIdx.x * 256 + tid;
    int c = (int)(i0 & 15) * 4;
    float s[4] = {0, 0, 0, 0}, q[4] = {0, 0, 0, 0};
    size_t stride = (size_t)gridDim.x * 256;
    size_t n = (size_t)NEDGE * 16;
    for (size_t idx = i0; idx < n; idx += stride) {
        float4 v = *(const float4*)&g_agg[idx << 2];
        s[0] += v.x; s[1] += v.y; s[2] += v.z; s[3] += v.w;
        q[0] += v.x * v.x; q[1] += v.y * v.y; q[2] += v.z * v.z; q[3] += v.w * v.w;
    }
#pragma unroll
    for (int u = 0; u < 4; u++) {
        atomicAdd(&sred[c + u], s[u]);
        atomicAdd(&sred[64 + c + u], q[u]);
    }
    __syncthreads();
    if (tid < 128) atomicAdd(&g_sumbuf[640 + tid], sred[tid]);
}

// ============================================================================
__global__ void k_stats2(const float* __restrict__ g22, const float* __restrict__ b22,
                         const float* __restrict__ g32, const float* __restrict__ b32) {
    int tid = threadIdx.x;  // 128
    if (tid < 64) {
        float mean = g_sumbuf[512 + tid] * (1.0f / NEDGE);
        float var  = g_sumbuf[576 + tid] * (1.0f / NEDGE) - mean * mean;
        float a = g22[tid] * rsqrtf(var + EPSF);
        g_ab[512 + tid] = a;
        g_ab[576 + tid] = b22[tid] - mean * a;
    } else {
        int c = tid - 64;
        float mean = g_sumbuf[640 + c] * (1.0f / NEDGE);
        float var  = g_sumbuf[704 + c] * (1.0f / NEDGE) - mean * mean;
        float a = g32[c] * rsqrtf(var + EPSF);
        g_ab[640 + c] = a;
        g_ab[704 + c] = b32[c] - mean * a;
    }
}

// ============================================================================
__global__ void __launch_bounds__(256) k_out(const float* __restrict__ edge,
                                             float* __restrict__ out) {
    size_t i0 = (size_t)blockIdx.x * 256 + threadIdx.x;
    int c = (int)(i0 & 15) * 4;
    float4 a2 = *(const float4*)&g_ab[512 + c];
    float4 b2v = *(const float4*)&g_ab[576 + c];
    float4 a3 = *(const float4*)&g_ab[640 + c];
    float4 b3v = *(const float4*)&g_ab[704 + c];
    size_t stride = (size_t)gridDim.x * 256;
    size_t n = (size_t)NEDGE * 16;
    for (size_t idx = i0; idx < n; idx += stride) {
        float4 e = *(const float4*)&edge[idx << 2];
        float4 g = *(const float4*)&g_g2[idx << 2];
        float4 a = *(const float4*)&g_agg[idx << 2];
        float4 o;
        o.x = tanhf(e.x + g.x * a2.x + b2v.x + a.x * a3.x + b3v.x);
        o.y = tanhf(e.y + g.y * a2.y + b2v.y + a.y * a3.y + b3v.y);
        o.z = tanhf(e.z + g.z * a2.z + b2v.z + a.z * a3.z + b3v.z);
        o.w = tanhf(e.w + g.w * a2.w + b2v.w + a.w * a3.w + b3v.w);
        *(float4*)&out[idx << 2] = o;
    }
}

// ============================================================================
extern "C" void kernel_launch(void* const* d_in, const int* in_sizes, int n_in,
                              void* d_out, int out_size) {
    const float* node = (const float*)d_in[0];
    const float* edge = (const float*)d_in[1];
    const int* vi     = (const int*)d_in[2];
    const int* vj     = (const int*)d_in[3];
    const int* idx_i  = (const int*)d_in[4];
    const int* idx_j  = (const int*)d_in[5];
    const int* idx_k  = (const int*)d_in[6];
    const int* idx_ji = (const int*)d_in[7];
    const int* idx_kj = (const int*)d_in[8];
    const float* W2   = (const float*)d_in[9];
    const float* b2   = (const float*)d_in[10];
    const float* W3   = (const float*)d_in[11];
    const float* gc2  = (const float*)d_in[13];
    const float* bc2  = (const float*)d_in[14];
    const float* gc3  = (const float*)d_in[15];
    const float* bc3  = (const float*)d_in[16];
    const float* g22  = (const float*)d_in[17];
    const float* b22  = (const float*)d_in[18];
    const float* g32  = (const float*)d_in[19];
    const float* b32  = (const float*)d_in[20];
    float* out = (float*)d_out;

    const int smem_k1 = (64 * CC + 64 * 72) * (int)sizeof(float);   // 51200 B
    cudaFuncSetAttribute(k_c2mm, cudaFuncAttributeMaxDynamicSharedMemorySize, smem_k1);
    cudaFuncSetAttribute(k_c3mm, cudaFuncAttributeMaxDynamicSharedMemorySize, SMEM_C3);

    k_zero<<<1024, 256>>>();
    k_prepw<<<160, 256>>>(W3);
    k_c2mm<<<592, 256, smem_k1>>>(node, vi, vj, W2, b2);
    k_c3mm<<<148, 256, SMEM_C3>>>(node, edge, idx_i, idx_j, idx_k, idx_ji, idx_kj);
    k_y3stats<<<1024, 256>>>();
    k_stats1<<<1, 256>>>(gc2, bc2, gc3, bc3);
    k_c2act<<<512, 256>>>();
    k_c3act<<<2048, 256>>>(idx_ji);
    k_aggstats<<<512, 256>>>();
    k_stats2<<<1, 128>>>(g22, b22, g32, b32);
    k_out<<<512, 256>>>(edge, out);
}

// round 8
// speedup vs baseline: 2.6831x; 1.2466x over previous
#include <cuda_runtime.h>
#include <cuda_bf16.h>
#include <cstdint>
#include <math.h>

#define HN 64
#define HE 64
#define NEDGE 200000
#define NTRI  600000
#define CC 128
#define D3 320
#define EPSF 1e-5f
#define TILE_M 128
#define NT_TILES ((NTRI + TILE_M - 1) / TILE_M)   // 4688
#define NE_TILES ((NEDGE + TILE_M - 1) / TILE_M)  // 1563

// ---------------- scratch ----------------
__device__ float g_y2[(size_t)NEDGE * CC];
__device__ float g_y3[(size_t)NTRI * CC];
__device__ float g_g2[(size_t)NEDGE * HE];
__device__ float g_agg[(size_t)NEDGE * HE];
__device__ unsigned short g_wbh[128 * 320];   // W3 hi bf16, panelized+swizzled
__device__ unsigned short g_wbl[128 * 320];   // W3 lo bf16
__device__ unsigned short g_w2h[128 * 64];    // W2 hi bf16
__device__ unsigned short g_w2l[128 * 64];    // W2 lo bf16
__device__ float g_sumbuf[768];
__device__ float g_ab[768];

// ---------------- helpers ----------------
__device__ __forceinline__ float sigmoidf_(float x) { return 1.0f / (1.0f + __expf(-x)); }
__device__ __forceinline__ uint32_t smem_u32(const void* p) {
    uint32_t a;
    asm("{ .reg .u64 t; cvta.to.shared.u64 t, %1; cvt.u32.u64 %0, t; }" : "=r"(a) : "l"(p));
    return a;
}
__device__ __forceinline__ uint32_t bfpack(float f0, float f1) {   // f0 -> low half
    uint32_t r;
    asm("cvt.rn.bf16x2.f32 %0, %1, %2;" : "=r"(r) : "f"(f1), "f"(f0));
    return r;
}
__device__ __forceinline__ void cvt_pair(float f0, float f1, uint32_t& h, uint32_t& l) {
    h = bfpack(f0, f1);
    float r0 = f0 - __uint_as_float((h & 0xFFFFu) << 16);
    float r1 = f1 - __uint_as_float(h & 0xFFFF0000u);
    l = bfpack(r0, r1);
}
__device__ __forceinline__ void ldsm_x4(uint32_t addr, uint32_t* r) {
    asm volatile("ldmatrix.sync.aligned.m8n8.x4.shared.b16 {%0,%1,%2,%3}, [%4];"
        : "=r"(r[0]), "=r"(r[1]), "=r"(r[2]), "=r"(r[3]) : "r"(addr));
}
__device__ __forceinline__ void mma_bf16(float* c, const uint32_t* a, const uint32_t* b) {
    asm volatile("mma.sync.aligned.m16n8k16.row.col.f32.bf16.bf16.f32 "
        "{%0,%1,%2,%3}, {%4,%5,%6,%7}, {%8,%9}, {%0,%1,%2,%3};"
        : "+f"(c[0]), "+f"(c[1]), "+f"(c[2]), "+f"(c[3])
        : "r"(a[0]), "r"(a[1]), "r"(a[2]), "r"(a[3]), "r"(b[0]), "r"(b[1]));
}
// A fragment ldmatrix address (M x K image, 128B rows, SW-XOR on bits[4:6])
__device__ __forceinline__ uint32_t a_addr(uint32_t base, int r0, int k0, int lane) {
    int row = r0 + (lane & 15);
    int kk = k0 + ((lane >> 4) << 3);
    return base + row * 128 + ((kk * 2) ^ ((row & 7) << 4));
}
// B fragment ldmatrix address (N x K image, covers 2 n8-tiles)
__device__ __forceinline__ uint32_t b_addr(uint32_t base, int n0, int k0, int lane) {
    int row = n0 + (lane & 7) + ((lane >> 4) << 3);
    int kk = k0 + (((lane >> 3) & 1) << 3);
    return base + row * 128 + ((kk * 2) ^ ((row & 7) << 4));
}

// c3 SMEM: W hi [0,81920), W lo [81920,163840), A bufs [163840, +65536)
#define SW_A 163840
#define SMEM_C3 (SW_A + 65536)   // 229376 B dynamic
// c2 SMEM: W2h [0,16KB), W2l [16KB,32KB), A bufs [32KB, 96KB)
#define SW2_A 32768
#define SMEM_C2 (SW2_A + 65536)  // 98304 B dynamic

// ============================================================================
__global__ void k_zero() {
    size_t i = (size_t)blockIdx.x * blockDim.x + threadIdx.x;
    size_t stride = (size_t)gridDim.x * blockDim.x;
    size_t n = (size_t)NEDGE * HE / 4;
    float4 z = make_float4(0.f, 0.f, 0.f, 0.f);
    float4* p4 = (float4*)g_agg;
    for (size_t p = i; p < n; p += stride) p4[p] = z;
    if (i < 768) g_sumbuf[i] = 0.0f;
}

// W3 bf16 hi/lo panelized swizzled images (panel p = k>>6)
__global__ void k_prepw(const float* __restrict__ W3) {
    int idx = blockIdx.x * 256 + threadIdx.x;
    if (idx >= 128 * 320) return;
    int n = idx / 320, k = idx - n * 320;
    float w = W3[idx];
    __nv_bfloat16 hb = __float2bfloat16_rn(w);
    __nv_bfloat16 lb = __float2bfloat16_rn(w - __bfloat162float(hb));
    int p = k >> 6, kk = k & 63;
    uint32_t byte = (uint32_t)p * 16384u + (uint32_t)n * 128u + (uint32_t)((kk * 2) ^ ((n & 7) << 4));
    g_wbh[byte >> 1] = __bfloat16_as_ushort(hb);
    g_wbl[byte >> 1] = __bfloat16_as_ushort(lb);
}
// W2 images (single K=64 panel)
__global__ void k_prepw2(const float* __restrict__ W2) {
    int idx = blockIdx.x * 256 + threadIdx.x;
    if (idx >= 128 * 64) return;
    int n = idx >> 6, k = idx & 63;
    float w = W2[idx];
    __nv_bfloat16 hb = __float2bfloat16_rn(w);
    __nv_bfloat16 lb = __float2bfloat16_rn(w - __bfloat162float(hb));
    uint32_t byte = (uint32_t)n * 128u + (uint32_t)((k * 2) ^ ((n & 7) << 4));
    g_w2h[byte >> 1] = __bfloat16_as_ushort(hb);
    g_w2l[byte >> 1] = __bfloat16_as_ushort(lb);
}

// ---------------- MMA panel bodies ----------------
// 16-warp variant: warp covers 32 rows x 32 cols, acc[2][4][4]
__device__ __forceinline__ void mma_panel16(uint32_t abase, uint32_t wbh, uint32_t wbl,
                                            int wm, int wn, int lane, float acc[2][4][4]) {
    uint32_t abl = abase + 16384;
#pragma unroll
    for (int ks = 0; ks < 4; ks++) {
        int k0 = ks * 16;
        uint32_t ah[2][4], al[2][4], bh[2][4], bl[2][4];
        ldsm_x4(a_addr(abase, wm * 32, k0, lane), ah[0]);
        ldsm_x4(a_addr(abase, wm * 32 + 16, k0, lane), ah[1]);
        ldsm_x4(a_addr(abl, wm * 32, k0, lane), al[0]);
        ldsm_x4(a_addr(abl, wm * 32 + 16, k0, lane), al[1]);
        ldsm_x4(b_addr(wbh, wn * 32, k0, lane), bh[0]);
        ldsm_x4(b_addr(wbh, wn * 32 + 16, k0, lane), bh[1]);
        ldsm_x4(b_addr(wbl, wn * 32, k0, lane), bl[0]);
        ldsm_x4(b_addr(wbl, wn * 32 + 16, k0, lane), bl[1]);
#pragma unroll
        for (int mt = 0; mt < 2; mt++)
#pragma unroll
            for (int g = 0; g < 2; g++) {
                mma_bf16(acc[mt][2 * g],     ah[mt], &bh[g][0]);
                mma_bf16(acc[mt][2 * g + 1], ah[mt], &bh[g][2]);
                mma_bf16(acc[mt][2 * g],     ah[mt], &bl[g][0]);
                mma_bf16(acc[mt][2 * g + 1], ah[mt], &bl[g][2]);
                mma_bf16(acc[mt][2 * g],     al[mt], &bh[g][0]);
                mma_bf16(acc[mt][2 * g + 1], al[mt], &bh[g][2]);
            }
    }
}
// 8-warp variant: warp covers 32 rows x 64 cols, acc[2][8][4]
__device__ __forceinline__ void mma_panel64(uint32_t abase, uint32_t wbh, uint32_t wbl,
                                            int wm, int wn, int lane, float acc[2][8][4]) {
    uint32_t abl = abase + 16384;
#pragma unroll
    for (int ks = 0; ks < 4; ks++) {
        int k0 = ks * 16;
        uint32_t ah[2][4], al[2][4];
        ldsm_x4(a_addr(abase, wm * 32, k0, lane), ah[0]);
        ldsm_x4(a_addr(abase, wm * 32 + 16, k0, lane), ah[1]);
        ldsm_x4(a_addr(abl, wm * 32, k0, lane), al[0]);
        ldsm_x4(a_addr(abl, wm * 32 + 16, k0, lane), al[1]);
        uint32_t bh[4][4], bl[4][4];
#pragma unroll
        for (int g = 0; g < 4; g++) {
            ldsm_x4(b_addr(wbh, wn * 64 + g * 16, k0, lane), bh[g]);
            ldsm_x4(b_addr(wbl, wn * 64 + g * 16, k0, lane), bl[g]);
        }
#pragma unroll
        for (int mt = 0; mt < 2; mt++)
#pragma unroll
            for (int g = 0; g < 4; g++) {
                mma_bf16(acc[mt][2 * g],     ah[mt], &bh[g][0]);
                mma_bf16(acc[mt][2 * g + 1], ah[mt], &bh[g][2]);
                mma_bf16(acc[mt][2 * g],     ah[mt], &bl[g][0]);
                mma_bf16(acc[mt][2 * g + 1], ah[mt], &bl[g][2]);
                mma_bf16(acc[mt][2 * g],     al[mt], &bh[g][0]);
                mma_bf16(acc[mt][2 * g + 1], al[mt], &bh[g][2]);
            }
    }
}

// ---------------- gathers ----------------
__device__ __forceinline__ void gather3(const float* __restrict__ src,
                                        const int* __restrict__ idx,
                                        int tbase, int tid, float4* v) {
    int r = tid >> 2, q = tid & 3;
    int t = tbase + r;
    if (t < NTRI) {
        const float4* sp = (const float4*)(src + (size_t)idx[t] * 64) + q * 4;
        v[0] = sp[0]; v[1] = sp[1]; v[2] = sp[2]; v[3] = sp[3];
    } else {
        v[0] = v[1] = v[2] = v[3] = make_float4(0.f, 0.f, 0.f, 0.f);
    }
}
__device__ __forceinline__ void cvt_store3(const float4* v, char* buf, int tid) {
    int r = tid >> 2, q = tid & 3;
    int swm = (r & 7) << 4;
#pragma unroll
    for (int i = 0; i < 4; i++) {
        uint32_t h0, l0, h1, l1;
        cvt_pair(v[i].x, v[i].y, h0, l0);
        cvt_pair(v[i].z, v[i].w, h1, l1);
        int off = r * 128 + ((q * 32 + i * 8) ^ swm);
        *(uint2*)(buf + off) = make_uint2(h0, h1);
        *(uint2*)(buf + 16384 + off) = make_uint2(l0, l1);
    }
}
__device__ __forceinline__ void gather2(const float* __restrict__ node,
                                        const int* __restrict__ vi,
                                        const int* __restrict__ vj,
                                        int tbase, int tid, float4* v) {
    int r = tid >> 1, h = tid & 1;
    int e = tbase + r;
    if (e < NEDGE) {
        const float4* a = (const float4*)(node + (size_t)vi[e] * 64) + h * 8;
        const float4* b = (const float4*)(node + (size_t)vj[e] * 64) + h * 8;
#pragma unroll
        for (int i = 0; i < 8; i++) {
            float4 x = a[i], y = b[i];
            v[i] = make_float4(x.x * y.x, x.y * y.y, x.z * y.z, x.w * y.w);
        }
    } else {
#pragma unroll
        for (int i = 0; i < 8; i++) v[i] = make_float4(0.f, 0.f, 0.f, 0.f);
    }
}
__device__ __forceinline__ void cvt_store2(const float4* v, char* buf, int tid) {
    int r = tid >> 1, h = tid & 1;
    int swm = (r & 7) << 4;
#pragma unroll
    for (int i = 0; i < 8; i++) {
        uint32_t h0, l0, h1, l1;
        cvt_pair(v[i].x, v[i].y, h0, l0);
        cvt_pair(v[i].z, v[i].w, h1, l1);
        int off = r * 128 + ((h * 64 + i * 8) ^ swm);
        *(uint2*)(buf + off) = make_uint2(h0, h1);
        *(uint2*)(buf + 16384 + off) = make_uint2(l0, l1);
    }
}

// ============================================================================
// K1: c2 linear via HMMA (K=64, 1 panel, cross-tile double buffer) + y2 stats
// ============================================================================
__global__ void __launch_bounds__(256, 1) k_c2mm(const float* __restrict__ node,
                                                 const int* __restrict__ vi,
                                                 const int* __restrict__ vj) {
    extern __shared__ __align__(128) char smal[];
    __shared__ float sred[256];
    const uint32_t sbal = smem_u32(smal);
    const int tid = threadIdx.x, wid = tid >> 5, lane = tid & 31;
    const int wm = wid >> 1, wn = wid & 1;
    {
        const uint4* srch = (const uint4*)g_w2h;
        const uint4* srcl = (const uint4*)g_w2l;
        uint4* dsth = (uint4*)smal;
        uint4* dstl = (uint4*)(smal + 16384);
        for (int i = tid; i < 1024; i += 256) { dsth[i] = srch[i]; dstl[i] = srcl[i]; }
    }
    sred[tid] = 0.0f;

    float4 v[8];
    int tile = blockIdx.x;
    if (tile < NE_TILES) {
        gather2(node, vi, vj, tile * TILE_M, tid, v);
        cvt_store2(v, smal + SW2_A, tid);
    }
    __syncthreads();
    uint32_t parOff = 0;
    const int lr = lane >> 2, lq = lane & 3;

    for (; tile < NE_TILES; tile += gridDim.x) {
        const int tbase = tile * TILE_M;
        float acc[2][8][4];
#pragma unroll
        for (int mt = 0; mt < 2; mt++)
#pragma unroll
            for (int nt = 0; nt < 8; nt++)
#pragma unroll
                for (int u = 0; u < 4; u++) acc[mt][nt][u] = 0.0f;

        int ntile = tile + gridDim.x;
        if (ntile < NE_TILES) gather2(node, vi, vj, ntile * TILE_M, tid, v);
        mma_panel64(sbal + SW2_A + parOff, sbal, sbal + 16384u, wm, wn, lane, acc);
        if (ntile < NE_TILES) cvt_store2(v, smal + SW2_A + (parOff ^ 32768u), tid);

        // epilogue: y2 stores + column stats
#pragma unroll
        for (int mt = 0; mt < 2; mt++) {
            int gr = tbase + wm * 32 + mt * 16 + lr;
#pragma unroll
            for (int nt = 0; nt < 8; nt++) {
                int col = wn * 64 + nt * 8 + lq * 2;
                if (gr < NEDGE)
                    *(float2*)&g_y2[(size_t)gr * CC + col] = make_float2(acc[mt][nt][0], acc[mt][nt][1]);
                if (gr + 8 < NEDGE)
                    *(float2*)&g_y2[(size_t)(gr + 8) * CC + col] = make_float2(acc[mt][nt][2], acc[mt][nt][3]);
            }
        }
        float sv[16], qv[16];
#pragma unroll
        for (int nt = 0; nt < 8; nt++)
#pragma unroll
            for (int j = 0; j < 2; j++) {
                float a0 = acc[0][nt][j], a1 = acc[0][nt][j + 2];
                float a2 = acc[1][nt][j], a3 = acc[1][nt][j + 2];
                sv[nt * 2 + j] = a0 + a1 + a2 + a3;
                qv[nt * 2 + j] = a0 * a0 + a1 * a1 + a2 * a2 + a3 * a3;
            }
#pragma unroll
        for (int i = 0; i < 16; i++) {
#pragma unroll
            for (int m = 4; m < 32; m <<= 1) {
                sv[i] += __shfl_xor_sync(0xffffffff, sv[i], m);
                qv[i] += __shfl_xor_sync(0xffffffff, qv[i], m);
            }
        }
        if (lane < 4) {
#pragma unroll
            for (int i = 0; i < 16; i++) {
                int col = wn * 64 + (i >> 1) * 8 + lane * 2 + (i & 1);
                atomicAdd(&sred[col], sv[i]);
                atomicAdd(&sred[128 + col], qv[i]);
            }
        }
        __syncthreads();
        parOff ^= 32768u;
    }
    __syncthreads();
    atomicAdd(&g_sumbuf[tid], sred[tid]);
}

// ============================================================================
// K2: c3 linear via HMMA, 512 threads / 16 warps + fused y3 stats
// ============================================================================
__global__ void __launch_bounds__(512, 1) k_c3mm(const float* __restrict__ node,
                                                 const float* __restrict__ edge,
                                                 const int* __restrict__ ii,
                                                 const int* __restrict__ ij,
                                                 const int* __restrict__ ik,
                                                 const int* __restrict__ iji,
                                                 const int* __restrict__ ikj) {
    extern __shared__ __align__(128) char smal[];
    __shared__ float sred[256];
    const uint32_t sbal = smem_u32(smal);
    const int tid = threadIdx.x, wid = tid >> 5, lane = tid & 31;
    const int wm = wid >> 2, wn = wid & 3;
    {
        const uint4* srch = (const uint4*)g_wbh;
        const uint4* srcl = (const uint4*)g_wbl;
        uint4* dsth = (uint4*)smal;
        uint4* dstl = (uint4*)(smal + 81920);
        for (int i = tid; i < 5120; i += 512) { dsth[i] = srch[i]; dstl[i] = srcl[i]; }
    }
    if (tid < 256) sred[tid] = 0.0f;

    float4 v[4];
    int tile = blockIdx.x;
    if (tile < NT_TILES) {
        gather3(node, ii, tile * TILE_M, tid, v);
        cvt_store3(v, smal + SW_A, tid);
    }
    __syncthreads();
    uint32_t parOff = 0;
    const int lr = lane >> 2, lq = lane & 3;

    for (; tile < NT_TILES; tile += gridDim.x) {
        const int tbase = tile * TILE_M;
        float acc[2][4][4];
#pragma unroll
        for (int mt = 0; mt < 2; mt++)
#pragma unroll
            for (int nt = 0; nt < 4; nt++)
#pragma unroll
                for (int u = 0; u < 4; u++) acc[mt][nt][u] = 0.0f;

        uint32_t A0 = sbal + SW_A + parOff;
        uint32_t A1 = sbal + SW_A + (parOff ^ 32768u);
        char* cA0 = smal + SW_A + parOff;
        char* cA1 = smal + SW_A + (parOff ^ 32768u);

        gather3(node, ij, tbase, tid, v);
        mma_panel16(A0, sbal, sbal + 81920u, wm, wn, lane, acc);
        cvt_store3(v, cA1, tid);
        __syncthreads();

        gather3(node, ik, tbase, tid, v);
        mma_panel16(A1, sbal + 16384u, sbal + 98304u, wm, wn, lane, acc);
        cvt_store3(v, cA0, tid);
        __syncthreads();

        gather3(edge, iji, tbase, tid, v);
        mma_panel16(A0, sbal + 32768u, sbal + 114688u, wm, wn, lane, acc);
        cvt_store3(v, cA1, tid);
        __syncthreads();

        gather3(edge, ikj, tbase, tid, v);
        mma_panel16(A1, sbal + 49152u, sbal + 131072u, wm, wn, lane, acc);
        cvt_store3(v, cA0, tid);
        __syncthreads();

        int ntile = tile + gridDim.x;
        if (ntile < NT_TILES) gather3(node, ii, ntile * TILE_M, tid, v);
        mma_panel16(A0, sbal + 65536u, sbal + 147456u, wm, wn, lane, acc);
        if (ntile < NT_TILES) cvt_store3(v, cA1, tid);

        // epilogue: y3 stores + fused column stats
#pragma unroll
        for (int mt = 0; mt < 2; mt++) {
            int gr = tbase + wm * 32 + mt * 16 + lr;
#pragma unroll
            for (int nt = 0; nt < 4; nt++) {
                int col = wn * 32 + nt * 8 + lq * 2;
                if (gr < NTRI)
                    *(float2*)&g_y3[(size_t)gr * CC + col] = make_float2(acc[mt][nt][0], acc[mt][nt][1]);
                if (gr + 8 < NTRI)
                    *(float2*)&g_y3[(size_t)(gr + 8) * CC + col] = make_float2(acc[mt][nt][2], acc[mt][nt][3]);
            }
        }
        float sv[8], qv[8];
#pragma unroll
        for (int nt = 0; nt < 4; nt++)
#pragma unroll
            for (int j = 0; j < 2; j++) {
                float a0 = acc[0][nt][j], a1 = acc[0][nt][j + 2];
                float a2 = acc[1][nt][j], a3 = acc[1][nt][j + 2];
                sv[nt * 2 + j] = a0 + a1 + a2 + a3;
                qv[nt * 2 + j] = a0 * a0 + a1 * a1 + a2 * a2 + a3 * a3;
            }
#pragma unroll
        for (int i = 0; i < 8; i++) {
#pragma unroll
            for (int m = 4; m < 32; m <<= 1) {
                sv[i] += __shfl_xor_sync(0xffffffff, sv[i], m);
                qv[i] += __shfl_xor_sync(0xffffffff, qv[i], m);
            }
        }
        if (lane < 4) {
#pragma unroll
            for (int i = 0; i < 8; i++) {
                int col = wn * 32 + (i >> 1) * 8 + lane * 2 + (i & 1);
                atomicAdd(&sred[col], sv[i]);
                atomicAdd(&sred[128 + col], qv[i]);
            }
        }
        __syncthreads();
        parOff ^= 32768u;
    }
    __syncthreads();
    if (tid < 256) atomicAdd(&g_sumbuf[256 + tid], sred[tid]);
}

// ============================================================================
__global__ void k_stats1(const float* __restrict__ gc2, const float* __restrict__ bc2,
                         const float* __restrict__ gc3, const float* __restrict__ bc3) {
    int tid = threadIdx.x;  // 256
    if (tid < 128) {
        float mean = g_sumbuf[tid] * (1.0f / NEDGE);
        float var  = g_sumbuf[128 + tid] * (1.0f / NEDGE) - mean * mean;
        float a = gc2[tid] * rsqrtf(var + EPSF);
        g_ab[tid] = a;
        g_ab[128 + tid] = bc2[tid] - mean * a;
    } else {
        int c = tid - 128;
        float mean = g_sumbuf[256 + c] * (1.0f / NTRI);
        float var  = g_sumbuf[384 + c] * (1.0f / NTRI) - mean * mean;
        float a = gc3[c] * rsqrtf(var + EPSF);
        g_ab[256 + c] = a;
        g_ab[384 + c] = bc3[c] - mean * a;
    }
}

// ============================================================================
__global__ void __launch_bounds__(256) k_c2act() {
    __shared__ float sred[128];
    int tid = threadIdx.x;
    if (tid < 128) sred[tid] = 0.0f;
    __syncthreads();
    size_t i0 = (size_t)blockIdx.x * 256 + tid;
    int c = (int)(i0 & 15) * 4;
    float4 af = *(const float4*)&g_ab[c];
    float4 bf = *(const float4*)&g_ab[128 + c];
    float4 ac = *(const float4*)&g_ab[64 + c];
    float4 bc = *(const float4*)&g_ab[192 + c];
    float s[4] = {0, 0, 0, 0}, q[4] = {0, 0, 0, 0};
    size_t stride = (size_t)gridDim.x * 256;
    size_t n = (size_t)NEDGE * 16;
    for (size_t idx = i0; idx < n; idx += stride) {
        size_t e = idx >> 4;
        float4 yf = *(const float4*)&g_y2[(e << 7) + c];
        float4 yc = *(const float4*)&g_y2[(e << 7) + 64 + c];
        float4 g;
        g.x = sigmoidf_(yf.x * af.x + bf.x) * tanhf(yc.x * ac.x + bc.x);
        g.y = sigmoidf_(yf.y * af.y + bf.y) * tanhf(yc.y * ac.y + bc.y);
        g.z = sigmoidf_(yf.z * af.z + bf.z) * tanhf(yc.z * ac.z + bc.z);
        g.w = sigmoidf_(yf.w * af.w + bf.w) * tanhf(yc.w * ac.w + bc.w);
        *(float4*)&g_g2[idx << 2] = g;
        s[0] += g.x; s[1] += g.y; s[2] += g.z; s[3] += g.w;
        q[0] += g.x * g.x; q[1] += g.y * g.y; q[2] += g.z * g.z; q[3] += g.w * g.w;
    }
#pragma unroll
    for (int u = 0; u < 4; u++) {
        atomicAdd(&sred[c + u], s[u]);
        atomicAdd(&sred[64 + c + u], q[u]);
    }
    __syncthreads();
    if (tid < 128) atomicAdd(&g_sumbuf[512 + tid], sred[tid]);
}

// ============================================================================
__global__ void __launch_bounds__(256) k_c3act(const int* __restrict__ iji) {
    size_t i0 = (size_t)blockIdx.x * 256 + threadIdx.x;
    int c = (int)(i0 & 15) * 4;
    float4 af = *(const float4*)&g_ab[256 + c];
    float4 bf = *(const float4*)&g_ab[384 + c];
    float4 ac = *(const float4*)&g_ab[320 + c];
    float4 bc = *(const float4*)&g_ab[448 + c];
    size_t stride = (size_t)gridDim.x * 256;
    size_t n = (size_t)NTRI * 16;
    for (size_t idx = i0; idx < n; idx += stride) {
        size_t t = idx >> 4;
        float4 yf = *(const float4*)&g_y3[(t << 7) + c];
        float4 yc = *(const float4*)&g_y3[(t << 7) + 64 + c];
        float m0 = sigmoidf_(yf.x * af.x + bf.x) * tanhf(yc.x * ac.x + bc.x);
        float m1 = sigmoidf_(yf.y * af.y + bf.y) * tanhf(yc.y * ac.y + bc.y);
        float m2 = sigmoidf_(yf.z * af.z + bf.z) * tanhf(yc.z * ac.z + bc.z);
        float m3 = sigmoidf_(yf.w * af.w + bf.w) * tanhf(yc.w * ac.w + bc.w);
        float* dst = g_agg + ((size_t)iji[t] << 6) + c;
        asm volatile("red.global.v4.f32.add [%0], {%1, %2, %3, %4};"
                     :: "l"(dst), "f"(m0), "f"(m1), "f"(m2), "f"(m3) : "memory");
    }
}

// ============================================================================
__global__ void __launch_bounds__(256) k_aggstats() {
    __shared__ float sred[128];
    int tid = threadIdx.x;
    if (tid < 128) sred[tid] = 0.0f;
    __syncthreads();
    size_t i0 = (size_t)blockIdx.x * 256 + tid;
    int c = (int)(i0 & 15) * 4;
    float s[4] = {0, 0, 0, 0}, q[4] = {0, 0, 0, 0};
    size_t stride = (size_t)gridDim.x * 256;
    size_t n = (size_t)NEDGE * 16;
    for (size_t idx = i0; idx < n; idx += stride) {
        float4 vv = *(const float4*)&g_agg[idx << 2];
        s[0] += vv.x; s[1] += vv.y; s[2] += vv.z; s[3] += vv.w;
        q[0] += vv.x * vv.x; q[1] += vv.y * vv.y; q[2] += vv.z * vv.z; q[3] += vv.w * vv.w;
    }
#pragma unroll
    for (int u = 0; u < 4; u++) {
        atomicAdd(&sred[c + u], s[u]);
        atomicAdd(&sred[64 + c + u], q[u]);
    }
    __syncthreads();
    if (tid < 128) atomicAdd(&g_sumbuf[640 + tid], sred[tid]);
}

// ============================================================================
__global__ void k_stats2(const float* __restrict__ g22, const float* __restrict__ b22,
                         const float* __restrict__ g32, const float* __restrict__ b32) {
    int tid = threadIdx.x;  // 128
    if (tid < 64) {
        float mean = g_sumbuf[512 + tid] * (1.0f / NEDGE);
        float var  = g_sumbuf[576 + tid] * (1.0f / NEDGE) - mean * mean;
        float a = g22[tid] * rsqrtf(var + EPSF);
        g_ab[512 + tid] = a;
        g_ab[576 + tid] = b22[tid] - mean * a;
    } else {
        int c = tid - 64;
        float mean = g_sumbuf[640 + c] * (1.0f / NEDGE);
        float var  = g_sumbuf[704 + c] * (1.0f / NEDGE) - mean * mean;
        float a = g32[c] * rsqrtf(var + EPSF);
        g_ab[640 + c] = a;
        g_ab[704 + c] = b32[c] - mean * a;
    }
}

// ============================================================================
__global__ void __launch_bounds__(256) k_out(const float* __restrict__ edge,
                                             float* __restrict__ out) {
    size_t i0 = (size_t)blockIdx.x * 256 + threadIdx.x;
    int c = (int)(i0 & 15) * 4;
    float4 a2 = *(const float4*)&g_ab[512 + c];
    float4 b2v = *(const float4*)&g_ab[576 + c];
    float4 a3 = *(const float4*)&g_ab[640 + c];
    float4 b3v = *(const float4*)&g_ab[704 + c];
    size_t stride = (size_t)gridDim.x * 256;
    size_t n = (size_t)NEDGE * 16;
    for (size_t idx = i0; idx < n; idx += stride) {
        float4 e = *(const float4*)&edge[idx << 2];
        float4 g = *(const float4*)&g_g2[idx << 2];
        float4 a = *(const float4*)&g_agg[idx << 2];
        float4 o;
        o.x = tanhf(e.x + g.x * a2.x + b2v.x + a.x * a3.x + b3v.x);
        o.y = tanhf(e.y + g.y * a2.y + b2v.y + a.y * a3.y + b3v.y);
        o.z = tanhf(e.z + g.z * a2.z + b2v.z + a.z * a3.z + b3v.z);
        o.w = tanhf(e.w + g.w * a2.w + b2v.w + a.w * a3.w + b3v.w);
        *(float4*)&out[idx << 2] = o;
    }
}

// ============================================================================
extern "C" void kernel_launch(void* const* d_in, const int* in_sizes, int n_in,
                              void* d_out, int out_size) {
    const float* node = (const float*)d_in[0];
    const float* edge = (const float*)d_in[1];
    const int* vi     = (const int*)d_in[2];
    const int* vj     = (const int*)d_in[3];
    const int* idx_i  = (const int*)d_in[4];
    const int* idx_j  = (const int*)d_in[5];
    const int* idx_k  = (const int*)d_in[6];
    const int* idx_ji = (const int*)d_in[7];
    const int* idx_kj = (const int*)d_in[8];
    const float* W2   = (const float*)d_in[9];
    const float* W3   = (const float*)d_in[11];
    const float* gc2  = (const float*)d_in[13];
    const float* bc2  = (const float*)d_in[14];
    const float* gc3  = (const float*)d_in[15];
    const float* bc3  = (const float*)d_in[16];
    const float* g22  = (const float*)d_in[17];
    const float* b22  = (const float*)d_in[18];
    const float* g32  = (const float*)d_in[19];
    const float* b32  = (const float*)d_in[20];
    float* out = (float*)d_out;

    cudaFuncSetAttribute(k_c2mm, cudaFuncAttributeMaxDynamicSharedMemorySize, SMEM_C2);
    cudaFuncSetAttribute(k_c3mm, cudaFuncAttributeMaxDynamicSharedMemorySize, SMEM_C3);

    k_zero<<<1024, 256>>>();
    k_prepw<<<160, 256>>>(W3);
    k_prepw2<<<32, 256>>>(W2);
    k_c2mm<<<148, 256, SMEM_C2>>>(node, vi, vj);
    k_c3mm<<<148, 512, SMEM_C3>>>(node, edge, idx_i, idx_j, idx_k, idx_ji, idx_kj);
    k_stats1<<<1, 256>>>(gc2, bc2, gc3, bc3);
    k_c2act<<<512, 256>>>();
    k_c3act<<<2048, 256>>>(idx_ji);
    k_aggstats<<<512, 256>>>();
    k_stats2<<<1, 128>>>(g22, b22, g32, b32);
    k_out<<<512, 256>>>(edge, out);
}